// round 1
// baseline (speedup 1.0000x reference)
#include <cuda_runtime.h>
#include <math.h>

#define THREADS 256

// feat[b][ch][pix], ch = c*81 + k, pix = y*8+x   (64 * 243 * 64 floats ~ 4MB)
static __device__ float g_feat[64 * 243 * 64];

struct Smem {
    float2 XF[1024];    // fft2(x)
    float2 W1[1024];    // work
    float2 W2[1024];    // work
    float2 U0F[1024];   // fft2(|ifft2(xf*psi0)|)
    float  U[1024];     // real work (x staging / u0)
    float  PHI[1024];   // phi (32x32)
    float  PHI1[256];   // sub(phi,2) (16x16)
    float2 A16[256];
    float2 B16[256];
    float  U16[256];
    float2 P8[64];
    float twc32[32], tws32[32];
    float twc16[16], tws16[16];
    float twc8[8],  tws8[8];
};

// ---------------- DFT building blocks (direct, two-pass) ----------------
// Twiddle tables hold cis(+2*pi*j/N). Forward uses w = c - i*t, inverse w = c + i*t.

template<int N, bool FWD>
__device__ __forceinline__ void dft_rows(const float2* __restrict__ in, float2* __restrict__ out,
                                         const float* __restrict__ twc, const float* __restrict__ tws) {
    for (int idx = threadIdx.x; idx < N * N; idx += THREADS) {
        const int r = idx / N, k = idx % N;
        const float2* row = in + r * N;
        float ar = 0.f, ai = 0.f;
#pragma unroll
        for (int n = 0; n < N; n++) {
            const int ph = (k * n) & (N - 1);
            const float c = twc[ph], t = tws[ph];
            const float2 v = row[n];
            if (FWD) { ar = fmaf(v.x, c, fmaf( v.y, t, ar)); ai = fmaf(v.y, c, fmaf(-v.x, t, ai)); }
            else     { ar = fmaf(v.x, c, fmaf(-v.y, t, ar)); ai = fmaf(v.y, c, fmaf( v.x, t, ai)); }
        }
        out[idx] = make_float2(ar, ai);
    }
}

// forward row pass on real input (half cost)
template<int N>
__device__ __forceinline__ void dft_rows_real_fwd(const float* __restrict__ in, float2* __restrict__ out,
                                                  const float* __restrict__ twc, const float* __restrict__ tws) {
    for (int idx = threadIdx.x; idx < N * N; idx += THREADS) {
        const int r = idx / N, k = idx % N;
        const float* row = in + r * N;
        float ar = 0.f, ai = 0.f;
#pragma unroll
        for (int n = 0; n < N; n++) {
            const int ph = (k * n) & (N - 1);
            const float v = row[n];
            ar = fmaf(v,  twc[ph], ar);
            ai = fmaf(v, -tws[ph], ai);
        }
        out[idx] = make_float2(ar, ai);
    }
}

template<int N, bool FWD>
__device__ __forceinline__ void dft_cols(const float2* __restrict__ in, float2* __restrict__ out,
                                         const float* __restrict__ twc, const float* __restrict__ tws,
                                         float scale) {
    for (int idx = threadIdx.x; idx < N * N; idx += THREADS) {
        const int k1 = idx / N, k2 = idx % N;
        float ar = 0.f, ai = 0.f;
#pragma unroll
        for (int m = 0; m < N; m++) {
            const int ph = (k1 * m) & (N - 1);
            const float c = twc[ph], t = tws[ph];
            const float2 v = in[m * N + k2];
            if (FWD) { ar = fmaf(v.x, c, fmaf( v.y, t, ar)); ai = fmaf(v.y, c, fmaf(-v.x, t, ai)); }
            else     { ar = fmaf(v.x, c, fmaf(-v.y, t, ar)); ai = fmaf(v.y, c, fmaf( v.x, t, ai)); }
        }
        out[idx] = make_float2(ar * scale, ai * scale);
    }
}

// inverse column pass fused with modulus: out = scale * |z|
template<int N>
__device__ __forceinline__ void dft_cols_abs_inv(const float2* __restrict__ in, float* __restrict__ out,
                                                 const float* __restrict__ twc, const float* __restrict__ tws,
                                                 float scale) {
    for (int idx = threadIdx.x; idx < N * N; idx += THREADS) {
        const int k1 = idx / N, k2 = idx % N;
        float ar = 0.f, ai = 0.f;
#pragma unroll
        for (int m = 0; m < N; m++) {
            const int ph = (k1 * m) & (N - 1);
            const float c = twc[ph], t = tws[ph];
            const float2 v = in[m * N + k2];
            ar = fmaf(v.x, c, fmaf(-v.y, t, ar));
            ai = fmaf(v.y, c, fmaf( v.x, t, ai));
        }
        out[idx] = scale * sqrtf(ar * ar + ai * ai);
    }
}

// periodize 32x32 spectrum S*phi down to 8x8 (sub_fourier(S*phi, 4))
__device__ __forceinline__ void p8_from32(Smem& sm, const float2* __restrict__ S) {
    const int tid = threadIdx.x;
    if (tid < 64) {
        const int u = tid >> 3, v = tid & 7;
        float ar = 0.f, ai = 0.f;
#pragma unroll
        for (int i = 0; i < 4; i++)
#pragma unroll
            for (int j = 0; j < 4; j++) {
                const int off = (8 * i + u) * 32 + 8 * j + v;
                const float p = sm.PHI[off];
                const float2 z = S[off];
                ar = fmaf(z.x, p, ar); ai = fmaf(z.y, p, ai);
            }
        sm.P8[tid] = make_float2(ar * 0.0625f, ai * 0.0625f);
    }
}

// ifft2 on 8x8 spectrum, real part only, scale 1/64, store to global
__device__ __forceinline__ void ifft8_store(Smem& sm, float* __restrict__ dst) {
    const int tid = threadIdx.x;
    if (tid < 64) {
        const int y = tid >> 3, xx = tid & 7;
        float acc = 0.f;
#pragma unroll
        for (int u = 0; u < 8; u++)
#pragma unroll
            for (int v = 0; v < 8; v++) {
                const int ph = (y * u + xx * v) & 7;
                const float2 p = sm.P8[u * 8 + v];
                acc = fmaf(p.x, sm.twc8[ph], fmaf(-p.y, sm.tws8[ph], acc));
            }
        dst[tid] = acc * (1.0f / 64.0f);
    }
}

// Full P16 pipeline: q = sub(S32*psi,2) -> u=|ifft16(q)| -> Uf=fft16(u)
//                    -> p8 = sub(Uf*phi1,2) -> s = Re(ifft8(p8)) -> dst
__device__ void p16_pipeline(Smem& sm, const float2* __restrict__ S32,
                             const float* __restrict__ ps, float* __restrict__ dst) {
    const int tid = threadIdx.x;
    {   // q16 build (exactly one element per thread)
        const int a = tid >> 4, b2 = tid & 15;
        float ar = 0.f, ai = 0.f;
#pragma unroll
        for (int i = 0; i < 2; i++)
#pragma unroll
            for (int j = 0; j < 2; j++) {
                const int off = (16 * i + a) * 32 + 16 * j + b2;
                const float p = ps[off];
                const float2 v = S32[off];
                ar = fmaf(v.x, p, ar); ai = fmaf(v.y, p, ai);
            }
        sm.A16[tid] = make_float2(0.25f * ar, 0.25f * ai);
    }
    __syncthreads();
    dft_rows<16, false>(sm.A16, sm.B16, sm.twc16, sm.tws16);
    __syncthreads();
    dft_cols_abs_inv<16>(sm.B16, sm.U16, sm.twc16, sm.tws16, 1.0f / 256.0f);
    __syncthreads();
    dft_rows_real_fwd<16>(sm.U16, sm.A16, sm.twc16, sm.tws16);
    __syncthreads();
    dft_cols<16, true>(sm.A16, sm.B16, sm.twc16, sm.tws16, 1.0f);
    __syncthreads();
    if (tid < 64) {
        const int u = tid >> 3, v = tid & 7;
        float ar = 0.f, ai = 0.f;
#pragma unroll
        for (int i = 0; i < 2; i++)
#pragma unroll
            for (int j = 0; j < 2; j++) {
                const int off = (8 * i + u) * 16 + 8 * j + v;
                const float p = sm.PHI1[off];
                const float2 z = sm.B16[off];
                ar = fmaf(z.x, p, ar); ai = fmaf(z.y, p, ai);
            }
        sm.P8[tid] = make_float2(0.25f * ar, 0.25f * ai);
    }
    __syncthreads();
    ifft8_store(sm, dst);
    __syncthreads();
}

// ---------------- main scattering kernel ----------------
// grid = 192 * 9 blocks: bc = blockIdx.x/9 in [0,192), role = blockIdx.x%9
// role 0: s0 + s1b[0..7];  role r=1..8: t1=r-1 -> s1a[t1] + s2[t1][0..7]
__global__ void __launch_bounds__(THREADS)
scatter_kernel(const float* __restrict__ x, const float* __restrict__ psi0,
               const float* __restrict__ psi1, const float* __restrict__ phi) {
    __shared__ Smem sm;
    const int tid = threadIdx.x;
    const int bc = blockIdx.x / 9;
    const int role = blockIdx.x - bc * 9;

    // twiddle tables
    if (tid < 32) {
        float s, c; sincospif((float)tid * (1.0f / 16.0f), &s, &c);
        sm.twc32[tid] = c; sm.tws32[tid] = s;
    } else if (tid < 48) {
        const int j = tid - 32;
        float s, c; sincospif((float)j * (1.0f / 8.0f), &s, &c);
        sm.twc16[j] = c; sm.tws16[j] = s;
    } else if (tid < 56) {
        const int j = tid - 48;
        float s, c; sincospif((float)j * 0.25f, &s, &c);
        sm.twc8[j] = c; sm.tws8[j] = s;
    }
    for (int i = tid; i < 1024; i += THREADS) sm.PHI[i] = phi[i];
    __syncthreads();
    for (int i = tid; i < 256; i += THREADS) {
        const int a = i >> 4, b2 = i & 15;
        sm.PHI1[i] = 0.25f * (sm.PHI[a * 32 + b2] + sm.PHI[(a + 16) * 32 + b2] +
                              sm.PHI[a * 32 + b2 + 16] + sm.PHI[(a + 16) * 32 + b2 + 16]);
    }
    const float* xin = x + bc * 1024;
    for (int i = tid; i < 1024; i += THREADS) sm.U[i] = xin[i];
    __syncthreads();

    // xf = fft2(x)
    dft_rows_real_fwd<32>(sm.U, sm.W1, sm.twc32, sm.tws32);
    __syncthreads();
    dft_cols<32, true>(sm.W1, sm.XF, sm.twc32, sm.tws32, 1.0f);
    __syncthreads();

    float* featbase = g_feat + bc * 81 * 64;

    if (role == 0) {
        // s0
        p8_from32(sm, sm.XF);
        __syncthreads();
        ifft8_store(sm, featbase + 0 * 64);
        __syncthreads();
        // s1b[t]
        for (int t = 0; t < 8; t++)
            p16_pipeline(sm, sm.XF, psi1 + t * 1024, featbase + (9 + t) * 64);
    } else {
        const int t1 = role - 1;
        // A = xf * psi0[t1]
        const float* ps = psi0 + t1 * 1024;
        for (int i = tid; i < 1024; i += THREADS) {
            const float p = ps[i];
            const float2 v = sm.XF[i];
            sm.W1[i] = make_float2(v.x * p, v.y * p);
        }
        __syncthreads();
        // u0 = |ifft2(A)|
        dft_rows<32, false>(sm.W1, sm.W2, sm.twc32, sm.tws32);
        __syncthreads();
        dft_cols_abs_inv<32>(sm.W2, sm.U, sm.twc32, sm.tws32, 1.0f / 1024.0f);
        __syncthreads();
        // u0f = fft2(u0)
        dft_rows_real_fwd<32>(sm.U, sm.W1, sm.twc32, sm.tws32);
        __syncthreads();
        dft_cols<32, true>(sm.W1, sm.U0F, sm.twc32, sm.tws32, 1.0f);
        __syncthreads();
        // s1a[t1]
        p8_from32(sm, sm.U0F);
        __syncthreads();
        ifft8_store(sm, featbase + (1 + t1) * 64);
        __syncthreads();
        // s2[t1][t2]
        for (int t2 = 0; t2 < 8; t2++)
            p16_pipeline(sm, sm.U0F, psi1 + t2 * 1024, featbase + (17 + t1 * 8 + t2) * 64);
    }
}

// ---------------- GroupNorm + Linear ----------------
// one block per batch element
__global__ void __launch_bounds__(THREADS)
gn_linear_kernel(const float* __restrict__ gamma, const float* __restrict__ beta,
                 const float* __restrict__ W, const float* __restrict__ bias,
                 float* __restrict__ out) {
    const int b = blockIdx.x;
    const int tid = threadIdx.x;
    const int lane = tid & 31, warp = tid >> 5;
    __shared__ float s_mu[27], s_rs[27];
    __shared__ float s_red[8 * 10];

    const float* f = g_feat + b * 15552;

    // group stats: 27 groups of 576 contiguous floats, warp per group
    for (int g = warp; g < 27; g += 8) {
        float s = 0.f, s2 = 0.f;
        const float* fg = f + g * 576;
        for (int i = lane; i < 576; i += 32) {
            const float v = fg[i];
            s += v; s2 = fmaf(v, v, s2);
        }
#pragma unroll
        for (int o = 16; o > 0; o >>= 1) {
            s  += __shfl_xor_sync(0xffffffffu, s,  o);
            s2 += __shfl_xor_sync(0xffffffffu, s2, o);
        }
        if (lane == 0) {
            const float m = s * (1.0f / 576.0f);
            s_mu[g] = m;
            s_rs[g] = rsqrtf(s2 * (1.0f / 576.0f) - m * m + 1e-5f);
        }
    }
    __syncthreads();

    float acc[10];
#pragma unroll
    for (int j = 0; j < 10; j++) acc[j] = 0.f;

    for (int i = tid; i < 15552; i += THREADS) {
        const int ch = i >> 6;
        const int g = ch / 9;
        const float nv = (f[i] - s_mu[g]) * s_rs[g] * gamma[ch] + beta[ch];
#pragma unroll
        for (int j = 0; j < 10; j++)
            acc[j] = fmaf(nv, W[j * 15552 + i], acc[j]);
    }
#pragma unroll
    for (int j = 0; j < 10; j++) {
        float v = acc[j];
#pragma unroll
        for (int o = 16; o > 0; o >>= 1) v += __shfl_xor_sync(0xffffffffu, v, o);
        if (lane == 0) s_red[warp * 10 + j] = v;
    }
    __syncthreads();
    if (tid < 10) {
        float v = bias[tid];
#pragma unroll
        for (int w2 = 0; w2 < 8; w2++) v += s_red[w2 * 10 + tid];
        out[b * 10 + tid] = v;
    }
}

// ---------------- launch ----------------
extern "C" void kernel_launch(void* const* d_in, const int* in_sizes, int n_in,
                              void* d_out, int out_size) {
    const float* x     = (const float*)d_in[0];
    const float* psi0  = (const float*)d_in[1];
    const float* psi1  = (const float*)d_in[2];
    const float* phi   = (const float*)d_in[3];
    const float* gamma = (const float*)d_in[4];
    const float* beta  = (const float*)d_in[5];
    const float* W     = (const float*)d_in[6];
    const float* bias  = (const float*)d_in[7];
    float* out = (float*)d_out;

    scatter_kernel<<<192 * 9, THREADS>>>(x, psi0, psi1, phi);
    gn_linear_kernel<<<64, THREADS>>>(gamma, beta, W, bias, out);
}

// round 2
// speedup vs baseline: 1.7433x; 1.7433x over previous
#include <cuda_runtime.h>
#include <math.h>

#define T256 256

// ---------------- global scratch (static, no allocation) ----------------
static __device__ float  g_feat[64 * 243 * 64];   // (b*3+c)*81*64 + ch*64 + pix
static __device__ float2 g_xf  [192 * 1024];      // fft2(x) per (b,c)
static __device__ float2 g_u0f [1536 * 1024];     // fft2(|ifft2(xf*psi0)|) per (bc,t1)
static __device__ float  g_mu  [64 * 27];
static __device__ float  g_rs  [64 * 27];
static __device__ float  g_part[64 * 9 * 10];

// ---------------- 32-point direct DFT passes, register-blocked ----------------
// mapping: lane = output column index, warp handles 4 rows/freqs {w, w+8, w+16, w+24}
// twiddle table tw[j] = {cos(2*pi*j/32), sin(2*pi*j/32)}; fwd: w = c - i s, inv: w = c + i s

__device__ __forceinline__ void fwd_rows_real32(const float* __restrict__ in, float2* __restrict__ out,
                                                const float2* __restrict__ tw) {
    const int lane = threadIdx.x & 31, warp = threadIdx.x >> 5;
    float ar[4] = {0,0,0,0}, ai[4] = {0,0,0,0};
#pragma unroll
    for (int n = 0; n < 32; n++) {
        const float2 w = tw[(lane * n) & 31];
#pragma unroll
        for (int i = 0; i < 4; i++) {
            const float v = in[(warp + 8 * i) * 32 + n];       // warp-broadcast
            ar[i] = fmaf(v,  w.x, ar[i]);
            ai[i] = fmaf(v, -w.y, ai[i]);
        }
    }
#pragma unroll
    for (int i = 0; i < 4; i++) out[(warp + 8 * i) * 32 + lane] = make_float2(ar[i], ai[i]);
}

__device__ __forceinline__ void inv_rows32(const float2* __restrict__ in, float2* __restrict__ out,
                                           const float2* __restrict__ tw) {
    const int lane = threadIdx.x & 31, warp = threadIdx.x >> 5;
    float ar[4] = {0,0,0,0}, ai[4] = {0,0,0,0};
#pragma unroll
    for (int n = 0; n < 32; n++) {
        const float2 w = tw[(lane * n) & 31];
#pragma unroll
        for (int i = 0; i < 4; i++) {
            const float2 v = in[(warp + 8 * i) * 32 + n];      // warp-broadcast
            ar[i] = fmaf(v.x, w.x, fmaf(-v.y, w.y, ar[i]));
            ai[i] = fmaf(v.y, w.x, fmaf( v.x, w.y, ai[i]));
        }
    }
#pragma unroll
    for (int i = 0; i < 4; i++) out[(warp + 8 * i) * 32 + lane] = make_float2(ar[i], ai[i]);
}

__device__ __forceinline__ void fwd_cols32(const float2* __restrict__ in, float2* __restrict__ out,
                                           const float2* __restrict__ tw) {
    const int lane = threadIdx.x & 31, warp = threadIdx.x >> 5;
    float ar[4] = {0,0,0,0}, ai[4] = {0,0,0,0};
#pragma unroll
    for (int m = 0; m < 32; m++) {
        const float2 v = in[m * 32 + lane];                    // conflict-free
#pragma unroll
        for (int i = 0; i < 4; i++) {
            const float2 w = tw[((warp + 8 * i) * m) & 31];    // warp-broadcast
            ar[i] = fmaf(v.x, w.x, fmaf( v.y, w.y, ar[i]));
            ai[i] = fmaf(v.y, w.x, fmaf(-v.x, w.y, ai[i]));
        }
    }
#pragma unroll
    for (int i = 0; i < 4; i++) out[(warp + 8 * i) * 32 + lane] = make_float2(ar[i], ai[i]);
}

__device__ __forceinline__ void inv_cols_abs32(const float2* __restrict__ in, float* __restrict__ out,
                                               const float2* __restrict__ tw, float scale) {
    const int lane = threadIdx.x & 31, warp = threadIdx.x >> 5;
    float ar[4] = {0,0,0,0}, ai[4] = {0,0,0,0};
#pragma unroll
    for (int m = 0; m < 32; m++) {
        const float2 v = in[m * 32 + lane];
#pragma unroll
        for (int i = 0; i < 4; i++) {
            const float2 w = tw[((warp + 8 * i) * m) & 31];
            ar[i] = fmaf(v.x, w.x, fmaf(-v.y, w.y, ar[i]));
            ai[i] = fmaf(v.y, w.x, fmaf( v.x, w.y, ai[i]));
        }
    }
#pragma unroll
    for (int i = 0; i < 4; i++)
        out[(warp + 8 * i) * 32 + lane] = scale * sqrtf(ar[i] * ar[i] + ai[i] * ai[i]);
}

// ---------------- 8x8 pieces ----------------
// sub4(S*phi): 64 threads
__device__ __forceinline__ void p8_from32(const float2* __restrict__ S, const float* __restrict__ PHI,
                                          float2* __restrict__ P8) {
    const int tid = threadIdx.x;
    if (tid < 64) {
        const int u = tid >> 3, v = tid & 7;
        float ar = 0.f, ai = 0.f;
#pragma unroll
        for (int i = 0; i < 4; i++)
#pragma unroll
            for (int j = 0; j < 4; j++) {
                const int off = (8 * i + u) * 32 + 8 * j + v;
                const float p = PHI[off];
                const float2 z = S[off];
                ar = fmaf(z.x, p, ar); ai = fmaf(z.y, p, ai);
            }
        P8[tid] = make_float2(ar * 0.0625f, ai * 0.0625f);
    }
}

// Re(ifft2) of 8x8 spectrum, 64 threads, store scaled by 1/64
__device__ __forceinline__ void ifft8_store64(const float2* __restrict__ P8, const float2* __restrict__ tw8,
                                              float* __restrict__ dst) {
    const int tid = threadIdx.x;
    if (tid < 64) {
        const int y = tid >> 3, xx = tid & 7;
        float acc = 0.f;
#pragma unroll
        for (int u = 0; u < 8; u++)
#pragma unroll
            for (int v = 0; v < 8; v++) {
                const int ph = (y * u + xx * v) & 7;
                const float2 p = P8[u * 8 + v];
                const float2 w = tw8[ph];
                acc = fmaf(p.x, w.x, fmaf(-p.y, w.y, acc));
            }
        dst[tid] = acc * (1.0f / 64.0f);
    }
}

// ---------------- 16-point direct DFT passes (256 threads, 1 point each) ----------------
__device__ __forceinline__ void dft16_rows_inv(const float2* __restrict__ in, float2* __restrict__ out,
                                               const float2* __restrict__ tw) {
    const int tid = threadIdx.x, r = tid >> 4, k = tid & 15;
    const float2* row = in + r * 16;
    float ar = 0.f, ai = 0.f;
#pragma unroll
    for (int n = 0; n < 16; n++) {
        const float2 w = tw[(k * n) & 15];
        const float2 v = row[n];
        ar = fmaf(v.x, w.x, fmaf(-v.y, w.y, ar));
        ai = fmaf(v.y, w.x, fmaf( v.x, w.y, ai));
    }
    out[tid] = make_float2(ar, ai);
}

__device__ __forceinline__ void dft16_cols_abs_inv(const float2* __restrict__ in, float* __restrict__ out,
                                                   const float2* __restrict__ tw, float scale) {
    const int tid = threadIdx.x, k1 = tid >> 4, k2 = tid & 15;
    float ar = 0.f, ai = 0.f;
#pragma unroll
    for (int m = 0; m < 16; m++) {
        const float2 w = tw[(k1 * m) & 15];
        const float2 v = in[m * 16 + k2];
        ar = fmaf(v.x, w.x, fmaf(-v.y, w.y, ar));
        ai = fmaf(v.y, w.x, fmaf( v.x, w.y, ai));
    }
    out[tid] = scale * sqrtf(ar * ar + ai * ai);
}

__device__ __forceinline__ void dft16_rows_real_fwd(const float* __restrict__ in, float2* __restrict__ out,
                                                    const float2* __restrict__ tw) {
    const int tid = threadIdx.x, r = tid >> 4, k = tid & 15;
    const float* row = in + r * 16;
    float ar = 0.f, ai = 0.f;
#pragma unroll
    for (int n = 0; n < 16; n++) {
        const float2 w = tw[(k * n) & 15];
        const float v = row[n];
        ar = fmaf(v,  w.x, ar);
        ai = fmaf(v, -w.y, ai);
    }
    out[tid] = make_float2(ar, ai);
}

__device__ __forceinline__ void dft16_cols_fwd(const float2* __restrict__ in, float2* __restrict__ out,
                                               const float2* __restrict__ tw) {
    const int tid = threadIdx.x, k1 = tid >> 4, k2 = tid & 15;
    float ar = 0.f, ai = 0.f;
#pragma unroll
    for (int m = 0; m < 16; m++) {
        const float2 w = tw[(k1 * m) & 15];
        const float2 v = in[m * 16 + k2];
        ar = fmaf(v.x, w.x, fmaf( v.y, w.y, ar));
        ai = fmaf(v.y, w.x, fmaf(-v.x, w.y, ai));
    }
    out[tid] = make_float2(ar, ai);
}

// ---------------- K1: xf = fft2(x); s0 ----------------
__global__ void __launch_bounds__(T256)
k1_xf(const float* __restrict__ x, const float* __restrict__ phi) {
    __shared__ float  U[1024];
    __shared__ float2 Z[1024];
    __shared__ float2 XF[1024];
    __shared__ float  PHI[1024];
    __shared__ float2 P8[64];
    __shared__ float2 tw32[32];
    __shared__ float2 tw8[8];
    const int tid = threadIdx.x, bc = blockIdx.x;

    if (tid < 32) { float s, c; sincospif((float)tid * (1.0f / 16.0f), &s, &c); tw32[tid] = make_float2(c, s); }
    else if (tid < 40) { const int j = tid - 32; float s, c; sincospif((float)j * 0.25f, &s, &c); tw8[j] = make_float2(c, s); }
    for (int i = tid; i < 1024; i += T256) { U[i] = x[bc * 1024 + i]; PHI[i] = phi[i]; }
    __syncthreads();

    fwd_rows_real32(U, Z, tw32);
    __syncthreads();
    fwd_cols32(Z, XF, tw32);
    __syncthreads();

    float2* dst = g_xf + bc * 1024;
    for (int i = tid; i < 1024; i += T256) dst[i] = XF[i];

    p8_from32(XF, PHI, P8);
    __syncthreads();
    ifft8_store64(P8, tw8, g_feat + bc * 81 * 64);
}

// ---------------- K2: u0f per (bc, t1); s1a ----------------
__global__ void __launch_bounds__(T256)
k2_u0f(const float* __restrict__ psi0, const float* __restrict__ phi) {
    __shared__ float2 Z1[1024];
    __shared__ float2 Z2[1024];
    __shared__ float  U[1024];
    __shared__ float  PHI[1024];
    __shared__ float2 P8[64];
    __shared__ float2 tw32[32];
    __shared__ float2 tw8[8];
    const int tid = threadIdx.x;
    const int bc = blockIdx.x >> 3, t1 = blockIdx.x & 7;

    if (tid < 32) { float s, c; sincospif((float)tid * (1.0f / 16.0f), &s, &c); tw32[tid] = make_float2(c, s); }
    else if (tid < 40) { const int j = tid - 32; float s, c; sincospif((float)j * 0.25f, &s, &c); tw8[j] = make_float2(c, s); }

    const float2* xf = g_xf + bc * 1024;
    const float*  ps = psi0 + t1 * 1024;
    for (int i = tid; i < 1024; i += T256) {
        const float2 v = xf[i];
        const float  p = ps[i];
        Z1[i] = make_float2(v.x * p, v.y * p);
        PHI[i] = phi[i];
    }
    __syncthreads();

    inv_rows32(Z1, Z2, tw32);
    __syncthreads();
    inv_cols_abs32(Z2, U, tw32, 1.0f / 1024.0f);
    __syncthreads();
    fwd_rows_real32(U, Z1, tw32);
    __syncthreads();
    fwd_cols32(Z1, Z2, tw32);            // Z2 = u0f
    __syncthreads();

    float2* dst = g_u0f + (bc * 8 + t1) * 1024;
    for (int i = tid; i < 1024; i += T256) dst[i] = Z2[i];

    p8_from32(Z2, PHI, P8);
    __syncthreads();
    ifft8_store64(P8, tw8, g_feat + bc * 81 * 64 + (1 + t1) * 64);
}

// ---------------- K3: one P16 pipeline per block ----------------
// blockIdx: bc = /72, r = %72.  r<8: src=xf, t2=r, ch=9+r.
// r>=8: t1=(r-8)/8, t2=(r-8)%8, src=u0f[bc][t1], ch=17+(r-8).
__global__ void __launch_bounds__(T256)
k3_p16(const float* __restrict__ psi1, const float* __restrict__ phi) {
    __shared__ float2 A[256];
    __shared__ float2 Bc[256];
    __shared__ float  Ur[256];       // also reused as reduction buffer
    __shared__ float  PHI1[256];
    __shared__ float2 P8[64];
    __shared__ float2 tw16[16];
    __shared__ float2 tw8[8];
    const int tid = threadIdx.x;
    const int bc = blockIdx.x / 72;
    const int r  = blockIdx.x - bc * 72;

    const float2* src;
    int ch, t2;
    if (r < 8) { src = g_xf + bc * 1024; t2 = r; ch = 9 + r; }
    else {
        const int t1 = (r - 8) >> 3;
        t2 = (r - 8) & 7;
        src = g_u0f + (bc * 8 + t1) * 1024;
        ch = 17 + (r - 8);
    }

    if (tid < 16) { float s, c; sincospif((float)tid * 0.125f, &s, &c); tw16[tid] = make_float2(c, s); }
    else if (tid < 24) { const int j = tid - 16; float s, c; sincospif((float)j * 0.25f, &s, &c); tw8[j] = make_float2(c, s); }

    // phi1 = sub2(phi)
    {
        const int a = tid >> 4, b2 = tid & 15;
        PHI1[tid] = 0.25f * (phi[a * 32 + b2] + phi[(a + 16) * 32 + b2] +
                             phi[a * 32 + b2 + 16] + phi[(a + 16) * 32 + b2 + 16]);
    }

    // q = sub2(S * psi1[t2])
    {
        const float* ps = psi1 + t2 * 1024;
        const int a = tid >> 4, b2 = tid & 15;
        float ar = 0.f, ai = 0.f;
#pragma unroll
        for (int i = 0; i < 2; i++)
#pragma unroll
            for (int j = 0; j < 2; j++) {
                const int off = (16 * i + a) * 32 + 16 * j + b2;
                const float p = ps[off];
                const float2 v = src[off];
                ar = fmaf(v.x, p, ar); ai = fmaf(v.y, p, ai);
            }
        A[tid] = make_float2(0.25f * ar, 0.25f * ai);
    }
    __syncthreads();

    dft16_rows_inv(A, Bc, tw16);
    __syncthreads();
    dft16_cols_abs_inv(Bc, Ur, tw16, 1.0f / 256.0f);
    __syncthreads();
    dft16_rows_real_fwd(Ur, A, tw16);
    __syncthreads();
    dft16_cols_fwd(A, Bc, tw16);
    __syncthreads();

    // p8 = sub2(Bc * phi1)
    if (tid < 64) {
        const int u = tid >> 3, v = tid & 7;
        float ar = 0.f, ai = 0.f;
#pragma unroll
        for (int i = 0; i < 2; i++)
#pragma unroll
            for (int j = 0; j < 2; j++) {
                const int off = (8 * i + u) * 16 + 8 * j + v;
                const float p = PHI1[off];
                const float2 z = Bc[off];
                ar = fmaf(z.x, p, ar); ai = fmaf(z.y, p, ai);
            }
        P8[tid] = make_float2(0.25f * ar, 0.25f * ai);
    }
    __syncthreads();

    // ifft8, 4-way split across threads (tid = o + 64*q, q handles u in {2q, 2q+1})
    {
        const int o = tid & 63, q = tid >> 6;
        const int y = o >> 3, xx = o & 7;
        float acc = 0.f;
#pragma unroll
        for (int uu = 0; uu < 2; uu++) {
            const int u = 2 * q + uu;
#pragma unroll
            for (int v = 0; v < 8; v++) {
                const int ph = (y * u + xx * v) & 7;
                const float2 p = P8[u * 8 + v];
                const float2 w = tw8[ph];
                acc = fmaf(p.x, w.x, fmaf(-p.y, w.y, acc));
            }
        }
        Ur[tid] = acc;
    }
    __syncthreads();
    if (tid < 64) {
        const float v = (Ur[tid] + Ur[tid + 64] + Ur[tid + 128] + Ur[tid + 192]) * (1.0f / 64.0f);
        g_feat[bc * 81 * 64 + ch * 64 + tid] = v;
    }
}

// ---------------- K4a: group stats (one block per (b, g)) ----------------
__global__ void __launch_bounds__(64)
k4_stats() {
    const int blk = blockIdx.x, tid = threadIdx.x;   // blk = b*27 + g
    const float* f = g_feat + blk * 576;
    float s = 0.f, s2 = 0.f;
#pragma unroll
    for (int i = tid; i < 576; i += 64) {
        const float v = f[i];
        s += v; s2 = fmaf(v, v, s2);
    }
#pragma unroll
    for (int o = 16; o > 0; o >>= 1) {
        s  += __shfl_xor_sync(0xffffffffu, s,  o);
        s2 += __shfl_xor_sync(0xffffffffu, s2, o);
    }
    __shared__ float r1[2], r2[2];
    if ((tid & 31) == 0) { r1[tid >> 5] = s; r2[tid >> 5] = s2; }
    __syncthreads();
    if (tid == 0) {
        s = r1[0] + r1[1]; s2 = r2[0] + r2[1];
        const float m = s * (1.0f / 576.0f);
        g_mu[blk] = m;
        g_rs[blk] = rsqrtf(s2 * (1.0f / 576.0f) - m * m + 1e-5f);
    }
}

// ---------------- K4b: partial GEMV (grid = 64 batches x 9 chunks) ----------------
__global__ void __launch_bounds__(T256)
k4_gemv(const float* __restrict__ gamma, const float* __restrict__ beta,
        const float* __restrict__ W) {
    const int b = blockIdx.x / 9, c = blockIdx.x - (blockIdx.x / 9) * 9;
    const int base = c * 1728;                    // 27 channels = 3 groups per chunk
    const float* f = g_feat + b * 15552;
    const float* mu = g_mu + b * 27;
    const float* rs = g_rs + b * 27;

    float acc[10];
#pragma unroll
    for (int j = 0; j < 10; j++) acc[j] = 0.f;

    for (int i = threadIdx.x; i < 1728; i += T256) {
        const int idx = base + i;
        const int ch = idx >> 6;
        const int g = 3 * c + ((i >> 6) / 9);
        const float nv = (f[idx] - mu[g]) * rs[g] * gamma[ch] + beta[ch];
#pragma unroll
        for (int j = 0; j < 10; j++)
            acc[j] = fmaf(nv, W[j * 15552 + idx], acc[j]);
    }

    __shared__ float red[8 * 10];
    const int lane = threadIdx.x & 31, wrp = threadIdx.x >> 5;
#pragma unroll
    for (int j = 0; j < 10; j++) {
        float v = acc[j];
#pragma unroll
        for (int o = 16; o > 0; o >>= 1) v += __shfl_xor_sync(0xffffffffu, v, o);
        if (lane == 0) red[wrp * 10 + j] = v;
    }
    __syncthreads();
    if (threadIdx.x < 10) {
        float v = 0.f;
#pragma unroll
        for (int w2 = 0; w2 < 8; w2++) v += red[w2 * 10 + threadIdx.x];
        g_part[(b * 9 + c) * 10 + threadIdx.x] = v;
    }
}

// ---------------- K4c: final reduce ----------------
__global__ void __launch_bounds__(640)
k4_out(const float* __restrict__ bias, float* __restrict__ out) {
    const int tid = threadIdx.x;
    if (tid < 640) {
        const int b = tid / 10, j = tid - b * 10;
        float v = bias[j];
#pragma unroll
        for (int c = 0; c < 9; c++) v += g_part[(b * 9 + c) * 10 + j];
        out[tid] = v;
    }
}

// ---------------- launch ----------------
extern "C" void kernel_launch(void* const* d_in, const int* in_sizes, int n_in,
                              void* d_out, int out_size) {
    const float* x     = (const float*)d_in[0];
    const float* psi0  = (const float*)d_in[1];
    const float* psi1  = (const float*)d_in[2];
    const float* phi   = (const float*)d_in[3];
    const float* gamma = (const float*)d_in[4];
    const float* beta  = (const float*)d_in[5];
    const float* W     = (const float*)d_in[6];
    const float* bias  = (const float*)d_in[7];
    float* out = (float*)d_out;

    k1_xf   <<<192,       T256>>>(x, phi);
    k2_u0f  <<<1536,      T256>>>(psi0, phi);
    k3_p16  <<<192 * 72,  T256>>>(psi1, phi);
    k4_stats<<<64 * 27,   64  >>>();
    k4_gemv <<<64 * 9,    T256>>>(gamma, beta, W);
    k4_out  <<<1,         640 >>>(bias, out);
}

// round 3
// speedup vs baseline: 4.4130x; 2.5314x over previous
#include <cuda_runtime.h>
#include <math.h>

#define T256 256
#define T128 128

// ---------------- global scratch (static, no allocation) ----------------
static __device__ float  g_feat[64 * 243 * 64];   // (b*3+c)*81*64 + ch*64 + pix
static __device__ float2 g_xf  [192 * 1024];      // fft2(x) per (b,c)
static __device__ float2 g_u0f [1536 * 1024];     // fft2(|ifft2(xf*psi0)|) per (bc,t1)

__device__ __forceinline__ int brevn(int i, int bits) {
    return (int)(__brev((unsigned)i) >> (32 - bits));
}

// ---------------- serial register-resident radix-2 DIF FFT ----------------
// natural-order input in v[], output v[i] = X[bitrev(i)] (store with brevn).
// tw[j] = cis(+2*pi*j/N). INV=true: e^{+i}, unscaled. INV=false: e^{-i}.
template<int N, bool INV>
__device__ __forceinline__ void fft_serial(float2* v, const float2* __restrict__ tw) {
#pragma unroll
    for (int m = N; m >= 2; m >>= 1) {
        const int half = m >> 1, step = N / m;
#pragma unroll
        for (int k0 = 0; k0 < N; k0 += m) {
#pragma unroll
            for (int j = 0; j < half; j++) {
                const int lo = k0 + j, hi = lo + half;
                const float2 a = v[lo], b = v[hi];
                const float2 d = make_float2(a.x - b.x, a.y - b.y);
                v[lo] = make_float2(a.x + b.x, a.y + b.y);
                if (j == 0) {
                    v[hi] = d;
                } else if (j * step == N / 4) {
                    v[hi] = INV ? make_float2(-d.y, d.x) : make_float2(d.y, -d.x);
                } else {
                    const float2 w = tw[j * step];
                    const float ws = INV ? w.y : -w.y;
                    v[hi] = make_float2(d.x * w.x - d.y * ws, d.y * w.x + d.x * ws);
                }
            }
        }
    }
}

// ---------------- k1 helpers (register-blocked direct DFT, small kernel) ----------------
__device__ __forceinline__ void fwd_rows_real32(const float* __restrict__ in, float2* __restrict__ out,
                                                const float2* __restrict__ tw) {
    const int lane = threadIdx.x & 31, warp = threadIdx.x >> 5;
    float ar[4] = {0,0,0,0}, ai[4] = {0,0,0,0};
#pragma unroll
    for (int n = 0; n < 32; n++) {
        const float2 w = tw[(lane * n) & 31];
#pragma unroll
        for (int i = 0; i < 4; i++) {
            const float v = in[(warp + 8 * i) * 32 + n];
            ar[i] = fmaf(v,  w.x, ar[i]);
            ai[i] = fmaf(v, -w.y, ai[i]);
        }
    }
#pragma unroll
    for (int i = 0; i < 4; i++) out[(warp + 8 * i) * 32 + lane] = make_float2(ar[i], ai[i]);
}

__device__ __forceinline__ void fwd_cols32(const float2* __restrict__ in, float2* __restrict__ out,
                                           const float2* __restrict__ tw) {
    const int lane = threadIdx.x & 31, warp = threadIdx.x >> 5;
    float ar[4] = {0,0,0,0}, ai[4] = {0,0,0,0};
#pragma unroll
    for (int m = 0; m < 32; m++) {
        const float2 v = in[m * 32 + lane];
#pragma unroll
        for (int i = 0; i < 4; i++) {
            const float2 w = tw[((warp + 8 * i) * m) & 31];
            ar[i] = fmaf(v.x, w.x, fmaf( v.y, w.y, ar[i]));
            ai[i] = fmaf(v.y, w.x, fmaf(-v.x, w.y, ai[i]));
        }
    }
#pragma unroll
    for (int i = 0; i < 4; i++) out[(warp + 8 * i) * 32 + lane] = make_float2(ar[i], ai[i]);
}

__device__ __forceinline__ void p8_from32(const float2* __restrict__ S, const float* __restrict__ PHI,
                                          float2* __restrict__ P8) {
    const int tid = threadIdx.x;
    if (tid < 64) {
        const int u = tid >> 3, v = tid & 7;
        float ar = 0.f, ai = 0.f;
#pragma unroll
        for (int i = 0; i < 4; i++)
#pragma unroll
            for (int j = 0; j < 4; j++) {
                const int off = (8 * i + u) * 32 + 8 * j + v;
                const float p = PHI[off];
                const float2 z = S[off];
                ar = fmaf(z.x, p, ar); ai = fmaf(z.y, p, ai);
            }
        P8[tid] = make_float2(ar * 0.0625f, ai * 0.0625f);
    }
}

__device__ __forceinline__ void ifft8_store64(const float2* __restrict__ P8, const float2* __restrict__ tw8,
                                              float* __restrict__ dst) {
    const int tid = threadIdx.x;
    if (tid < 64) {
        const int y = tid >> 3, xx = tid & 7;
        float acc = 0.f;
#pragma unroll
        for (int u = 0; u < 8; u++)
#pragma unroll
            for (int v = 0; v < 8; v++) {
                const int ph = (y * u + xx * v) & 7;
                const float2 p = P8[u * 8 + v];
                const float2 w = tw8[ph];
                acc = fmaf(p.x, w.x, fmaf(-p.y, w.y, acc));
            }
        dst[tid] = acc * (1.0f / 64.0f);
    }
}

// ---------------- K1: xf = fft2(x); s0 ----------------
__global__ void __launch_bounds__(T256)
k1_xf(const float* __restrict__ x, const float* __restrict__ phi) {
    __shared__ float  U[1024];
    __shared__ float2 Z[1024];
    __shared__ float2 XF[1024];
    __shared__ float  PHI[1024];
    __shared__ float2 P8[64];
    __shared__ float2 tw32[32];
    __shared__ float2 tw8[8];
    const int tid = threadIdx.x, bc = blockIdx.x;

    if (tid < 32) { float s, c; sincospif((float)tid * (1.0f / 16.0f), &s, &c); tw32[tid] = make_float2(c, s); }
    else if (tid < 40) { const int j = tid - 32; float s, c; sincospif((float)j * 0.25f, &s, &c); tw8[j] = make_float2(c, s); }
    for (int i = tid; i < 1024; i += T256) { U[i] = x[bc * 1024 + i]; PHI[i] = phi[i]; }
    __syncthreads();

    fwd_rows_real32(U, Z, tw32);
    __syncthreads();
    fwd_cols32(Z, XF, tw32);
    __syncthreads();

    float2* dst = g_xf + bc * 1024;
    for (int i = tid; i < 1024; i += T256) dst[i] = XF[i];

    p8_from32(XF, PHI, P8);
    __syncthreads();
    ifft8_store64(P8, tw8, g_feat + bc * 81 * 64);
}

// ---------------- K2: u0f per (bc, t1); s1a -------------
// grid = 192*2, block = 128 threads; 4 t1 tiles per block, one warp per tile.
// Each thread owns a full 32-point line (row/col) in registers; passes are in-place.
__global__ void __launch_bounds__(T128)
k2_u0f(const float* __restrict__ psi0, const float* __restrict__ phi) {
    __shared__ float2 Z[4][32 * 33];     // padded stride 33: conflict-free column passes
    __shared__ float2 XF[32 * 33];
    __shared__ float  PHI[1024];
    __shared__ float2 P8s[4][64];
    __shared__ float2 tw32[32];
    __shared__ float2 tw8[8];
    const int tid = threadIdx.x;
    const int bc = blockIdx.x >> 1, half = blockIdx.x & 1;
    const int tt = tid >> 5, lane = tid & 31;
    const int t1 = half * 4 + tt;

    if (tid < 32) { float s, c; sincospif((float)tid * (1.0f / 16.0f), &s, &c); tw32[tid] = make_float2(c, s); }
    else if (tid < 40) { const int j = tid - 32; float s, c; sincospif((float)j * 0.25f, &s, &c); tw8[j] = make_float2(c, s); }

    const float2* xf = g_xf + bc * 1024;
    for (int i = tid; i < 1024; i += T128) {
        XF[(i >> 5) * 33 + (i & 31)] = xf[i];
        PHI[i] = phi[i];
    }
    __syncthreads();

    float2 v[32];
    // row pass (inverse) on xf * psi0[t1]
    {
        const float* ps = psi0 + t1 * 1024 + lane * 32;
#pragma unroll
        for (int n = 0; n < 32; n++) {
            const float p = ps[n];
            const float2 z = XF[lane * 33 + n];
            v[n] = make_float2(z.x * p, z.y * p);
        }
    }
    fft_serial<32, true>(v, tw32);
#pragma unroll
    for (int n = 0; n < 32; n++) Z[tt][lane * 33 + brevn(n, 5)] = v[n];
    __syncthreads();

    // col pass (inverse) + modulus -> u (real, stored in .x)
#pragma unroll
    for (int m = 0; m < 32; m++) v[m] = Z[tt][m * 33 + lane];
    fft_serial<32, true>(v, tw32);
#pragma unroll
    for (int m = 0; m < 32; m++) {
        const float u = sqrtf(v[m].x * v[m].x + v[m].y * v[m].y) * (1.0f / 1024.0f);
        Z[tt][brevn(m, 5) * 33 + lane] = make_float2(u, 0.f);
    }
    __syncthreads();

    // fwd rows on real u
#pragma unroll
    for (int n = 0; n < 32; n++) v[n] = make_float2(Z[tt][lane * 33 + n].x, 0.f);
    fft_serial<32, false>(v, tw32);
#pragma unroll
    for (int n = 0; n < 32; n++) Z[tt][lane * 33 + brevn(n, 5)] = v[n];
    __syncthreads();

    // fwd cols -> u0f (natural order)
#pragma unroll
    for (int m = 0; m < 32; m++) v[m] = Z[tt][m * 33 + lane];
    fft_serial<32, false>(v, tw32);
#pragma unroll
    for (int m = 0; m < 32; m++) Z[tt][brevn(m, 5) * 33 + lane] = v[m];
    __syncthreads();

    // write u0f to gmem (L2-resident for k3)
    {
        float2* dst = g_u0f + (bc * 8 + t1) * 1024;
#pragma unroll
        for (int m = 0; m < 32; m++) dst[m * 32 + lane] = Z[tt][m * 33 + lane];
    }

    // s1a: p8 = sub4(u0f * phi); s = Re(ifft8(p8))
#pragma unroll
    for (int k = 0; k < 2; k++) {
        const int o = lane + 32 * k;
        const int u = o >> 3, vv = o & 7;
        float ar = 0.f, ai = 0.f;
#pragma unroll
        for (int i = 0; i < 4; i++)
#pragma unroll
            for (int j = 0; j < 4; j++) {
                const float p = PHI[(8 * i + u) * 32 + 8 * j + vv];
                const float2 z = Z[tt][(8 * i + u) * 33 + 8 * j + vv];
                ar = fmaf(z.x, p, ar); ai = fmaf(z.y, p, ai);
            }
        P8s[tt][o] = make_float2(ar * 0.0625f, ai * 0.0625f);
    }
    __syncwarp();
#pragma unroll
    for (int k = 0; k < 2; k++) {
        const int o = lane + 32 * k;
        const int y = o >> 3, xx = o & 7;
        float acc = 0.f;
#pragma unroll
        for (int u = 0; u < 8; u++)
#pragma unroll
            for (int w2 = 0; w2 < 8; w2++) {
                const int ph = (y * u + xx * w2) & 7;
                const float2 p = P8s[tt][u * 8 + w2];
                const float2 w = tw8[ph];
                acc = fmaf(p.x, w.x, fmaf(-p.y, w.y, acc));
            }
        g_feat[bc * 81 * 64 + (1 + t1) * 64 + o] = acc * (1.0f / 64.0f);
    }
}

// ---------------- K3: all 8 t2 tiles per (bc, src) block ----------------
// grid = 192*9: role 0 -> src=xf (s1b), role r=1..8 -> src=u0f[r-1] (s2 row).
__global__ void __launch_bounds__(T128)
k3_p16(const float* __restrict__ psi1, const float* __restrict__ phi) {
    __shared__ float2 SRC[1024];
    __shared__ float2 Q[8][16 * 17];     // padded stride 17
    __shared__ float  PHI1[256];
    __shared__ float2 P8s[8][64];
    __shared__ float2 tw16[16];
    __shared__ float2 tw8[8];
    const int tid = threadIdx.x;
    const int bc = blockIdx.x / 9;
    const int role = blockIdx.x - bc * 9;

    const float2* src = (role == 0) ? (g_xf + bc * 1024) : (g_u0f + (bc * 8 + role - 1) * 1024);
    const int chbase = (role == 0) ? 9 : 17 + (role - 1) * 8;

    if (tid < 16) { float s, c; sincospif((float)tid * 0.125f, &s, &c); tw16[tid] = make_float2(c, s); }
    else if (tid < 24) { const int j = tid - 16; float s, c; sincospif((float)j * 0.25f, &s, &c); tw8[j] = make_float2(c, s); }

    for (int i = tid; i < 1024; i += T128) SRC[i] = src[i];
#pragma unroll
    for (int k = 0; k < 2; k++) {
        const int idx = tid + 128 * k;
        const int a = idx >> 4, b2 = idx & 15;
        PHI1[idx] = 0.25f * (phi[a * 32 + b2] + phi[(a + 16) * 32 + b2] +
                             phi[a * 32 + b2 + 16] + phi[(a + 16) * 32 + b2 + 16]);
    }
    __syncthreads();

    // q[t2] = sub2(SRC * psi1[t2]) for all 8 tiles
#pragma unroll
    for (int k = 0; k < 16; k++) {
        const int idx = tid + 128 * k;
        const int tile = idx >> 8, e = idx & 255;
        const int a = e >> 4, b2 = e & 15;
        const float* ps = psi1 + tile * 1024;
        float ar = 0.f, ai = 0.f;
#pragma unroll
        for (int i = 0; i < 2; i++)
#pragma unroll
            for (int j = 0; j < 2; j++) {
                const int off = (16 * i + a) * 32 + 16 * j + b2;
                const float p = ps[off];
                const float2 z = SRC[off];
                ar = fmaf(z.x, p, ar); ai = fmaf(z.y, p, ai);
            }
        Q[tile][a * 17 + b2] = make_float2(0.25f * ar, 0.25f * ai);
    }
    __syncthreads();

    float2 v[16];
    const int tile = tid >> 4, ln = tid & 15;

    // rows inverse
#pragma unroll
    for (int n = 0; n < 16; n++) v[n] = Q[tile][ln * 17 + n];
    fft_serial<16, true>(v, tw16);
#pragma unroll
    for (int n = 0; n < 16; n++) Q[tile][ln * 17 + brevn(n, 4)] = v[n];
    __syncthreads();

    // cols inverse + modulus
#pragma unroll
    for (int m = 0; m < 16; m++) v[m] = Q[tile][m * 17 + ln];
    fft_serial<16, true>(v, tw16);
#pragma unroll
    for (int m = 0; m < 16; m++) {
        const float u = sqrtf(v[m].x * v[m].x + v[m].y * v[m].y) * (1.0f / 256.0f);
        Q[tile][brevn(m, 4) * 17 + ln] = make_float2(u, 0.f);
    }
    __syncthreads();

    // fwd rows (real input)
#pragma unroll
    for (int n = 0; n < 16; n++) v[n] = make_float2(Q[tile][ln * 17 + n].x, 0.f);
    fft_serial<16, false>(v, tw16);
#pragma unroll
    for (int n = 0; n < 16; n++) Q[tile][ln * 17 + brevn(n, 4)] = v[n];
    __syncthreads();

    // fwd cols
#pragma unroll
    for (int m = 0; m < 16; m++) v[m] = Q[tile][m * 17 + ln];
    fft_serial<16, false>(v, tw16);
#pragma unroll
    for (int m = 0; m < 16; m++) Q[tile][brevn(m, 4) * 17 + ln] = v[m];
    __syncthreads();

    // p8 = sub2(spec * phi1) for all tiles
#pragma unroll
    for (int k = 0; k < 4; k++) {
        const int idx = tid + 128 * k;
        const int t = idx >> 6, o = idx & 63;
        const int u = o >> 3, vv = o & 7;
        float ar = 0.f, ai = 0.f;
#pragma unroll
        for (int i = 0; i < 2; i++)
#pragma unroll
            for (int j = 0; j < 2; j++) {
                const float p = PHI1[(8 * i + u) * 16 + 8 * j + vv];
                const float2 z = Q[t][(8 * i + u) * 17 + 8 * j + vv];
                ar = fmaf(z.x, p, ar); ai = fmaf(z.y, p, ai);
            }
        P8s[t][o] = make_float2(0.25f * ar, 0.25f * ai);
    }
    __syncthreads();

    // ifft8 (real part) + store
    float* fb = g_feat + bc * 81 * 64;
#pragma unroll
    for (int k = 0; k < 4; k++) {
        const int idx = tid + 128 * k;
        const int t = idx >> 6, o = idx & 63;
        const int y = o >> 3, xx = o & 7;
        float acc = 0.f;
#pragma unroll
        for (int u = 0; u < 8; u++)
#pragma unroll
            for (int w2 = 0; w2 < 8; w2++) {
                const int ph = (y * u + xx * w2) & 7;
                const float2 p = P8s[t][u * 8 + w2];
                const float2 w = tw8[ph];
                acc = fmaf(p.x, w.x, fmaf(-p.y, w.y, acc));
            }
        fb[(chbase + t) * 64 + o] = acc * (1.0f / 64.0f);
    }
}

// ---------------- K4: init + fused stats/GEMV with atomic finish ----------------
__global__ void __launch_bounds__(640)
k4_init(const float* __restrict__ bias, float* __restrict__ out) {
    const int t = threadIdx.x;
    if (t < 640) out[t] = bias[t % 10];
}

__global__ void __launch_bounds__(T256)
k4_gemv(const float* __restrict__ gamma, const float* __restrict__ beta,
        const float* __restrict__ W, float* __restrict__ out) {
    const int b = blockIdx.x / 9, c = blockIdx.x - (blockIdx.x / 9) * 9;
    const float* f = g_feat + b * 15552 + c * 1728;   // 3 complete groups of 576
    __shared__ float smu[3], srs[3];
    __shared__ float redA[3][2], redB[3][2];
    const int tid = threadIdx.x;

    if (tid < 192) {
        const int g = tid >> 6, l = tid & 63;
        float s = 0.f, s2 = 0.f;
#pragma unroll
        for (int i = l; i < 576; i += 64) {
            const float xv = f[g * 576 + i];
            s += xv; s2 = fmaf(xv, xv, s2);
        }
#pragma unroll
        for (int o = 16; o > 0; o >>= 1) {
            s  += __shfl_xor_sync(0xffffffffu, s,  o);
            s2 += __shfl_xor_sync(0xffffffffu, s2, o);
        }
        if ((l & 31) == 0) { redA[g][l >> 5] = s; redB[g][l >> 5] = s2; }
    }
    __syncthreads();
    if (tid < 3) {
        const float s = redA[tid][0] + redA[tid][1];
        const float s2 = redB[tid][0] + redB[tid][1];
        const float m = s * (1.0f / 576.0f);
        smu[tid] = m;
        srs[tid] = rsqrtf(s2 * (1.0f / 576.0f) - m * m + 1e-5f);
    }
    __syncthreads();

    float acc[10];
#pragma unroll
    for (int j = 0; j < 10; j++) acc[j] = 0.f;
    const float* Wc = W + c * 1728;
    for (int i = tid; i < 1728; i += T256) {
        const int l = i >> 6;
        const int gl = l / 9;
        const int ch = c * 27 + l;
        const float nv = (f[i] - smu[gl]) * srs[gl] * gamma[ch] + beta[ch];
#pragma unroll
        for (int j = 0; j < 10; j++)
            acc[j] = fmaf(nv, Wc[j * 15552 + i], acc[j]);
    }

    __shared__ float red[8][10];
    const int lane = tid & 31, wrp = tid >> 5;
#pragma unroll
    for (int j = 0; j < 10; j++) {
        float vv = acc[j];
#pragma unroll
        for (int o = 16; o > 0; o >>= 1) vv += __shfl_xor_sync(0xffffffffu, vv, o);
        if (lane == 0) red[wrp][j] = vv;
    }
    __syncthreads();
    if (tid < 10) {
        float vv = 0.f;
#pragma unroll
        for (int w = 0; w < 8; w++) vv += red[w][tid];
        atomicAdd(&out[b * 10 + tid], vv);
    }
}

// ---------------- launch ----------------
extern "C" void kernel_launch(void* const* d_in, const int* in_sizes, int n_in,
                              void* d_out, int out_size) {
    const float* x     = (const float*)d_in[0];
    const float* psi0  = (const float*)d_in[1];
    const float* psi1  = (const float*)d_in[2];
    const float* phi   = (const float*)d_in[3];
    const float* gamma = (const float*)d_in[4];
    const float* beta  = (const float*)d_in[5];
    const float* W     = (const float*)d_in[6];
    const float* bias  = (const float*)d_in[7];
    float* out = (float*)d_out;

    k4_init<<<1,        640 >>>(bias, out);
    k1_xf  <<<192,      T256>>>(x, phi);
    k2_u0f <<<384,      T128>>>(psi0, phi);
    k3_p16 <<<192 * 9,  T128>>>(psi1, phi);
    k4_gemv<<<64 * 9,   T256>>>(gamma, beta, W, out);
}

// round 4
// speedup vs baseline: 5.1176x; 1.1597x over previous
#include <cuda_runtime.h>
#include <math.h>

#define T256 256
#define T128 128

// ---------------- global scratch (static, no allocation) ----------------
static __device__ float  g_feat[64 * 243 * 64];   // (b*3+c)*81*64 + ch*64 + pix
static __device__ float2 g_xf  [192 * 1024];      // fft2(x) per (b,c)
static __device__ float2 g_u0f [1536 * 1024];     // fft2(|ifft2(xf*psi0)|) per (bc,t1)

__device__ __forceinline__ int brevn(int i, int bits) {
    return (int)(__brev((unsigned)i) >> (32 - bits));
}

// ---------------- serial register-resident radix-2 DIF FFT ----------------
// natural-order input in v[], output v[i] = X[bitrev(i)] (store with brevn).
// tw[j] = cis(+2*pi*j/N). INV=true: e^{+i}, unscaled. INV=false: e^{-i}.
template<int N, bool INV>
__device__ __forceinline__ void fft_serial(float2* v, const float2* __restrict__ tw) {
#pragma unroll
    for (int m = N; m >= 2; m >>= 1) {
        const int half = m >> 1, step = N / m;
#pragma unroll
        for (int k0 = 0; k0 < N; k0 += m) {
#pragma unroll
            for (int j = 0; j < half; j++) {
                const int lo = k0 + j, hi = lo + half;
                const float2 a = v[lo], b = v[hi];
                const float2 d = make_float2(a.x - b.x, a.y - b.y);
                v[lo] = make_float2(a.x + b.x, a.y + b.y);
                if (j == 0) {
                    v[hi] = d;
                } else if (j * step == N / 4) {
                    v[hi] = INV ? make_float2(-d.y, d.x) : make_float2(d.y, -d.x);
                } else {
                    const float2 w = tw[j * step];
                    const float ws = INV ? w.y : -w.y;
                    v[hi] = make_float2(d.x * w.x - d.y * ws, d.y * w.x + d.x * ws);
                }
            }
        }
    }
}

// ---------------- k1 helpers (register-blocked direct DFT, small kernel) ----------------
__device__ __forceinline__ void fwd_rows_real32(const float* __restrict__ in, float2* __restrict__ out,
                                                const float2* __restrict__ tw) {
    const int lane = threadIdx.x & 31, warp = threadIdx.x >> 5;
    float ar[4] = {0,0,0,0}, ai[4] = {0,0,0,0};
#pragma unroll
    for (int n = 0; n < 32; n++) {
        const float2 w = tw[(lane * n) & 31];
#pragma unroll
        for (int i = 0; i < 4; i++) {
            const float v = in[(warp + 8 * i) * 32 + n];
            ar[i] = fmaf(v,  w.x, ar[i]);
            ai[i] = fmaf(v, -w.y, ai[i]);
        }
    }
#pragma unroll
    for (int i = 0; i < 4; i++) out[(warp + 8 * i) * 32 + lane] = make_float2(ar[i], ai[i]);
}

__device__ __forceinline__ void fwd_cols32(const float2* __restrict__ in, float2* __restrict__ out,
                                           const float2* __restrict__ tw) {
    const int lane = threadIdx.x & 31, warp = threadIdx.x >> 5;
    float ar[4] = {0,0,0,0}, ai[4] = {0,0,0,0};
#pragma unroll
    for (int m = 0; m < 32; m++) {
        const float2 v = in[m * 32 + lane];
#pragma unroll
        for (int i = 0; i < 4; i++) {
            const float2 w = tw[((warp + 8 * i) * m) & 31];
            ar[i] = fmaf(v.x, w.x, fmaf( v.y, w.y, ar[i]));
            ai[i] = fmaf(v.y, w.x, fmaf(-v.x, w.y, ai[i]));
        }
    }
#pragma unroll
    for (int i = 0; i < 4; i++) out[(warp + 8 * i) * 32 + lane] = make_float2(ar[i], ai[i]);
}

__device__ __forceinline__ void p8_from32(const float2* __restrict__ S, const float* __restrict__ PHI,
                                          float2* __restrict__ P8) {
    const int tid = threadIdx.x;
    if (tid < 64) {
        const int u = tid >> 3, v = tid & 7;
        float ar = 0.f, ai = 0.f;
#pragma unroll
        for (int i = 0; i < 4; i++)
#pragma unroll
            for (int j = 0; j < 4; j++) {
                const int off = (8 * i + u) * 32 + 8 * j + v;
                const float p = PHI[off];
                const float2 z = S[off];
                ar = fmaf(z.x, p, ar); ai = fmaf(z.y, p, ai);
            }
        P8[tid] = make_float2(ar * 0.0625f, ai * 0.0625f);
    }
}

__device__ __forceinline__ void ifft8_store64(const float2* __restrict__ P8, const float2* __restrict__ tw8,
                                              float* __restrict__ dst) {
    const int tid = threadIdx.x;
    if (tid < 64) {
        const int y = tid >> 3, xx = tid & 7;
        float acc = 0.f;
#pragma unroll
        for (int u = 0; u < 8; u++)
#pragma unroll
            for (int v = 0; v < 8; v++) {
                const int ph = (y * u + xx * v) & 7;
                const float2 p = P8[u * 8 + v];
                const float2 w = tw8[ph];
                acc = fmaf(p.x, w.x, fmaf(-p.y, w.y, acc));
            }
        dst[tid] = acc * (1.0f / 64.0f);
    }
}

// ---------------- K1: xf = fft2(x); s0 ----------------
__global__ void __launch_bounds__(T256)
k1_xf(const float* __restrict__ x, const float* __restrict__ phi) {
    __shared__ float  U[1024];
    __shared__ float2 Z[1024];
    __shared__ float2 XF[1024];
    __shared__ float  PHI[1024];
    __shared__ float2 P8[64];
    __shared__ float2 tw32[32];
    __shared__ float2 tw8[8];
    const int tid = threadIdx.x, bc = blockIdx.x;

    if (tid < 32) { float s, c; sincospif((float)tid * (1.0f / 16.0f), &s, &c); tw32[tid] = make_float2(c, s); }
    else if (tid < 40) { const int j = tid - 32; float s, c; sincospif((float)j * 0.25f, &s, &c); tw8[j] = make_float2(c, s); }
    for (int i = tid; i < 1024; i += T256) { U[i] = x[bc * 1024 + i]; PHI[i] = phi[i]; }
    __syncthreads();

    fwd_rows_real32(U, Z, tw32);
    __syncthreads();
    fwd_cols32(Z, XF, tw32);
    __syncthreads();

    float2* dst = g_xf + bc * 1024;
    for (int i = tid; i < 1024; i += T256) dst[i] = XF[i];

    p8_from32(XF, PHI, P8);
    __syncthreads();
    ifft8_store64(P8, tw8, g_feat + bc * 81 * 64);
}

// ---------------- K2: u0f per (bc, t1); s1a — forward-packed pairs ----------------
// grid = 384 (bc, half), block = 128 (4 warps, warp w -> tile t1 = half*4+w).
// Inverse+modulus per tile; then pairs (4h+0,4h+1),(4h+2,4h+3) packed through the
// forward transform; spectra unpacked via conjugate symmetry on store.
__global__ void __launch_bounds__(T128)
k2_u0f(const float* __restrict__ psi0, const float* __restrict__ phi) {
    __shared__ float2 XF[32 * 33];
    __shared__ float2 ZW[4][32 * 33];   // per-warp inverse work; ZW[0..1] reused as packed buffers
    __shared__ float  PHI[1024];
    __shared__ float2 P8s[2][64];
    __shared__ float2 tw32[32];
    __shared__ float2 tw8[8];
    const int tid = threadIdx.x;
    const int bc = blockIdx.x >> 1, half = blockIdx.x & 1;
    const int w = tid >> 5, lane = tid & 31;
    const int t1 = half * 4 + w;

    if (tid < 32) { float s, c; sincospif((float)tid * (1.0f / 16.0f), &s, &c); tw32[tid] = make_float2(c, s); }
    else if (tid < 40) { const int j = tid - 32; float s, c; sincospif((float)j * 0.25f, &s, &c); tw8[j] = make_float2(c, s); }

    const float2* xf = g_xf + bc * 1024;
    for (int i = tid; i < 1024; i += T128) {
        XF[(i >> 5) * 33 + (i & 31)] = xf[i];
        PHI[i] = phi[i];
    }
    __syncthreads();

    float2 v[32];
    // inverse rows on xf * psi0[t1]
    {
        const float* ps = psi0 + t1 * 1024 + lane * 32;
#pragma unroll
        for (int n = 0; n < 32; n++) {
            const float p = ps[n];
            const float2 z = XF[lane * 33 + n];
            v[n] = make_float2(z.x * p, z.y * p);
        }
    }
    fft_serial<32, true>(v, tw32);
#pragma unroll
    for (int n = 0; n < 32; n++) ZW[w][lane * 33 + brevn(n, 5)] = v[n];
    __syncthreads();

    // inverse cols + modulus -> u kept in registers (v[m].x)
#pragma unroll
    for (int m = 0; m < 32; m++) v[m] = ZW[w][m * 33 + lane];
    fft_serial<32, true>(v, tw32);
#pragma unroll
    for (int m = 0; m < 32; m++)
        v[m].x = sqrtf(v[m].x * v[m].x + v[m].y * v[m].y) * (1.0f / 1024.0f);
    __syncthreads();   // all inverse reads done before packed overwrite of ZW[0..1]

    // packed write: pair p = w>>1, component = w&1
    {
        float* dstf = (float*)ZW[w >> 1];
        const int comp = w & 1;
#pragma unroll
        for (int m = 0; m < 32; m++)
            dstf[(brevn(m, 5) * 33 + lane) * 2 + comp] = v[m].x;
    }
    __syncthreads();

    // forward rows on packed u (64 lines: p=tid>>5, ln=tid&31)
    if (tid < 64) {
        const int p = tid >> 5, ln = tid & 31;
#pragma unroll
        for (int n = 0; n < 32; n++) v[n] = ZW[p][ln * 33 + n];
        fft_serial<32, false>(v, tw32);
#pragma unroll
        for (int n = 0; n < 32; n++) ZW[p][ln * 33 + brevn(n, 5)] = v[n];
    }
    __syncthreads();

    // forward cols (packed) -> natural order spectrum Z
    if (tid < 64) {
        const int p = tid >> 5, ln = tid & 31;
#pragma unroll
        for (int m = 0; m < 32; m++) v[m] = ZW[p][m * 33 + ln];
        fft_serial<32, false>(v, tw32);
#pragma unroll
        for (int m = 0; m < 32; m++) ZW[p][brevn(m, 5) * 33 + ln] = v[m];
    }
    __syncthreads();

    // unpack via conjugate symmetry, store both u0f spectra
    if (tid < 64) {
        const int p = tid >> 5, ln = tid & 31;
        const int lnn = (32 - ln) & 31;
        float2* dstA = g_u0f + (bc * 8 + half * 4 + 2 * p) * 1024;
        float2* dstB = dstA + 1024;
#pragma unroll
        for (int m = 0; m < 32; m++) {
            const float2 z1 = ZW[p][m * 33 + ln];
            const float2 z2 = ZW[p][(((32 - m) & 31)) * 33 + lnn];
            dstA[m * 32 + ln] = make_float2(0.5f * (z1.x + z2.x), 0.5f * (z1.y - z2.y));
            dstB[m * 32 + ln] = make_float2(0.5f * (z1.y + z2.y), 0.5f * (z2.x - z1.x));
        }
    }
    __syncthreads();

    // s1a packed: p8 = sub4(Z*phi), one point per thread (2 pairs x 64)
    {
        const int pp = tid >> 6, o = tid & 63;
        const int u = o >> 3, vv = o & 7;
        float ar = 0.f, ai = 0.f;
#pragma unroll
        for (int i = 0; i < 4; i++)
#pragma unroll
            for (int j = 0; j < 4; j++) {
                const float p = PHI[(8 * i + u) * 32 + 8 * j + vv];
                const float2 z = ZW[pp][(8 * i + u) * 33 + 8 * j + vv];
                ar = fmaf(z.x, p, ar); ai = fmaf(z.y, p, ai);
            }
        P8s[pp][o] = make_float2(ar * 0.0625f, ai * 0.0625f);
    }
    __syncthreads();

    // complex ifft8 of packed p8: Re -> even tile, Im -> odd tile
    {
        const int pp = tid >> 6, o = tid & 63;
        const int y = o >> 3, xx = o & 7;
        float ar = 0.f, ai = 0.f;
#pragma unroll
        for (int u = 0; u < 8; u++)
#pragma unroll
            for (int w2 = 0; w2 < 8; w2++) {
                const int ph = (y * u + xx * w2) & 7;
                const float2 p = P8s[pp][u * 8 + w2];
                const float2 tw = tw8[ph];
                ar = fmaf(p.x, tw.x, fmaf(-p.y, tw.y, ar));
                ai = fmaf(p.y, tw.x, fmaf( p.x, tw.y, ai));
            }
        float* fb = g_feat + bc * 81 * 64 + (1 + half * 4 + 2 * pp) * 64;
        fb[o]      = ar * (1.0f / 64.0f);
        fb[64 + o] = ai * (1.0f / 64.0f);
    }
}

// ---------------- K3: 8 t2 tiles per (bc, src) block, forward-packed pairs ----------------
// grid = 192*9: role 0 -> src=xf (s1b), role r=1..8 -> src=u0f[r-1] (s2 row).
__global__ void __launch_bounds__(T128)
k3_p16(const float* __restrict__ psi1, const float* __restrict__ phi) {
    __shared__ float2 SRC[1024];
    __shared__ float2 Q[8][16 * 17];     // per-tile spectra (inverse side)
    __shared__ float2 UP[4][16 * 17];    // packed forward work
    __shared__ float  PHI1[256];
    __shared__ float2 P8s[4][64];
    __shared__ float2 tw16[16];
    __shared__ float2 tw8[8];
    const int tid = threadIdx.x;
    const int bc = blockIdx.x / 9;
    const int role = blockIdx.x - bc * 9;

    const float2* src = (role == 0) ? (g_xf + bc * 1024) : (g_u0f + (bc * 8 + role - 1) * 1024);
    const int chbase = (role == 0) ? 9 : 17 + (role - 1) * 8;

    if (tid < 16) { float s, c; sincospif((float)tid * 0.125f, &s, &c); tw16[tid] = make_float2(c, s); }
    else if (tid < 24) { const int j = tid - 16; float s, c; sincospif((float)j * 0.25f, &s, &c); tw8[j] = make_float2(c, s); }

    for (int i = tid; i < 1024; i += T128) SRC[i] = src[i];
#pragma unroll
    for (int k = 0; k < 2; k++) {
        const int idx = tid + 128 * k;
        const int a = idx >> 4, b2 = idx & 15;
        PHI1[idx] = 0.25f * (phi[a * 32 + b2] + phi[(a + 16) * 32 + b2] +
                             phi[a * 32 + b2 + 16] + phi[(a + 16) * 32 + b2 + 16]);
    }
    __syncthreads();

    // Stage A: q[t2] = sub2(SRC * psi1[t2]) for all 8 tiles
#pragma unroll 4
    for (int k = 0; k < 16; k++) {
        const int idx = tid + 128 * k;
        const int tile = idx >> 8, e = idx & 255;
        const int a = e >> 4, b2 = e & 15;
        const float* ps = psi1 + tile * 1024;
        float ar = 0.f, ai = 0.f;
#pragma unroll
        for (int i = 0; i < 2; i++)
#pragma unroll
            for (int j = 0; j < 2; j++) {
                const int off = (16 * i + a) * 32 + 16 * j + b2;
                const float p = ps[off];
                const float2 z = SRC[off];
                ar = fmaf(z.x, p, ar); ai = fmaf(z.y, p, ai);
            }
        Q[tile][a * 17 + b2] = make_float2(0.25f * ar, 0.25f * ai);
    }
    __syncthreads();

    float2 v[16];
    const int tile = tid >> 4, ln = tid & 15;

    // Stage B: rows inverse (per tile)
#pragma unroll
    for (int n = 0; n < 16; n++) v[n] = Q[tile][ln * 17 + n];
    fft_serial<16, true>(v, tw16);
#pragma unroll
    for (int n = 0; n < 16; n++) Q[tile][ln * 17 + brevn(n, 4)] = v[n];
    __syncthreads();

    // Stage C: cols inverse + modulus, packed store into UP (component tile&1)
#pragma unroll
    for (int m = 0; m < 16; m++) v[m] = Q[tile][m * 17 + ln];
    fft_serial<16, true>(v, tw16);
    {
        float* upf = (float*)UP[tile >> 1];
        const int comp = tile & 1;
#pragma unroll
        for (int m = 0; m < 16; m++) {
            const float u = sqrtf(v[m].x * v[m].x + v[m].y * v[m].y) * (1.0f / 256.0f);
            upf[(brevn(m, 4) * 17 + ln) * 2 + comp] = u;
        }
    }
    __syncthreads();

    // Stage D: rows fwd on packed u (4 pairs x 16 lines = 64 lines)
    if (tid < 64) {
        const int p = tid >> 4, l2 = tid & 15;
#pragma unroll
        for (int n = 0; n < 16; n++) v[n] = UP[p][l2 * 17 + n];
        fft_serial<16, false>(v, tw16);
#pragma unroll
        for (int n = 0; n < 16; n++) UP[p][l2 * 17 + brevn(n, 4)] = v[n];
    }
    __syncthreads();

    // Stage E: cols fwd (packed) -> natural-order packed spectrum
    if (tid < 64) {
        const int p = tid >> 4, l2 = tid & 15;
#pragma unroll
        for (int m = 0; m < 16; m++) v[m] = UP[p][m * 17 + l2];
        fft_serial<16, false>(v, tw16);
#pragma unroll
        for (int m = 0; m < 16; m++) UP[p][brevn(m, 4) * 17 + l2] = v[m];
    }
    __syncthreads();

    // Stage F: p8 = sub2(Zpacked * phi1), 4 pairs x 64 points
#pragma unroll
    for (int k = 0; k < 2; k++) {
        const int idx = tid + 128 * k;
        const int pp = idx >> 6, o = idx & 63;
        const int u = o >> 3, vv = o & 7;
        float ar = 0.f, ai = 0.f;
#pragma unroll
        for (int i = 0; i < 2; i++)
#pragma unroll
            for (int j = 0; j < 2; j++) {
                const float p = PHI1[(8 * i + u) * 16 + 8 * j + vv];
                const float2 z = UP[pp][(8 * i + u) * 17 + 8 * j + vv];
                ar = fmaf(z.x, p, ar); ai = fmaf(z.y, p, ai);
            }
        P8s[pp][o] = make_float2(0.25f * ar, 0.25f * ai);
    }
    __syncthreads();

    // Stage G: complex ifft8; Re -> even tile channel, Im -> odd tile channel
    float* fb = g_feat + bc * 81 * 64;
#pragma unroll
    for (int k = 0; k < 2; k++) {
        const int idx = tid + 128 * k;
        const int pp = idx >> 6, o = idx & 63;
        const int y = o >> 3, xx = o & 7;
        float ar = 0.f, ai = 0.f;
#pragma unroll
        for (int u = 0; u < 8; u++)
#pragma unroll
            for (int w2 = 0; w2 < 8; w2++) {
                const int ph = (y * u + xx * w2) & 7;
                const float2 p = P8s[pp][u * 8 + w2];
                const float2 w = tw8[ph];
                ar = fmaf(p.x, w.x, fmaf(-p.y, w.y, ar));
                ai = fmaf(p.y, w.x, fmaf( p.x, w.y, ai));
            }
        fb[(chbase + 2 * pp)     * 64 + o] = ar * (1.0f / 64.0f);
        fb[(chbase + 2 * pp + 1) * 64 + o] = ai * (1.0f / 64.0f);
    }
}

// ---------------- K4: init + fused stats/GEMV with atomic finish ----------------
__global__ void __launch_bounds__(640)
k4_init(const float* __restrict__ bias, float* __restrict__ out) {
    const int t = threadIdx.x;
    if (t < 640) out[t] = bias[t % 10];
}

__global__ void __launch_bounds__(T256)
k4_gemv(const float* __restrict__ gamma, const float* __restrict__ beta,
        const float* __restrict__ W, float* __restrict__ out) {
    const int b = blockIdx.x / 9, c = blockIdx.x - (blockIdx.x / 9) * 9;
    const float* f = g_feat + b * 15552 + c * 1728;   // 3 complete groups of 576
    __shared__ float smu[3], srs[3];
    __shared__ float redA[3][2], redB[3][2];
    const int tid = threadIdx.x;

    if (tid < 192) {
        const int g = tid >> 6, l = tid & 63;
        float s = 0.f, s2 = 0.f;
#pragma unroll
        for (int i = l; i < 576; i += 64) {
            const float xv = f[g * 576 + i];
            s += xv; s2 = fmaf(xv, xv, s2);
        }
#pragma unroll
        for (int o = 16; o > 0; o >>= 1) {
            s  += __shfl_xor_sync(0xffffffffu, s,  o);
            s2 += __shfl_xor_sync(0xffffffffu, s2, o);
        }
        if ((l & 31) == 0) { redA[g][l >> 5] = s; redB[g][l >> 5] = s2; }
    }
    __syncthreads();
    if (tid < 3) {
        const float s = redA[tid][0] + redA[tid][1];
        const float s2 = redB[tid][0] + redB[tid][1];
        const float m = s * (1.0f / 576.0f);
        smu[tid] = m;
        srs[tid] = rsqrtf(s2 * (1.0f / 576.0f) - m * m + 1e-5f);
    }
    __syncthreads();

    float acc[10];
#pragma unroll
    for (int j = 0; j < 10; j++) acc[j] = 0.f;
    const float* Wc = W + c * 1728;
    for (int i = tid; i < 1728; i += T256) {
        const int l = i >> 6;
        const int gl = l / 9;
        const int ch = c * 27 + l;
        const float nv = (f[i] - smu[gl]) * srs[gl] * gamma[ch] + beta[ch];
#pragma unroll
        for (int j = 0; j < 10; j++)
            acc[j] = fmaf(nv, Wc[j * 15552 + i], acc[j]);
    }

    __shared__ float red[8][10];
    const int lane = tid & 31, wrp = tid >> 5;
#pragma unroll
    for (int j = 0; j < 10; j++) {
        float vv = acc[j];
#pragma unroll
        for (int o = 16; o > 0; o >>= 1) vv += __shfl_xor_sync(0xffffffffu, vv, o);
        if (lane == 0) red[wrp][j] = vv;
    }
    __syncthreads();
    if (tid < 10) {
        float vv = 0.f;
#pragma unroll
        for (int w = 0; w < 8; w++) vv += red[w][tid];
        atomicAdd(&out[b * 10 + tid], vv);
    }
}

// ---------------- launch ----------------
extern "C" void kernel_launch(void* const* d_in, const int* in_sizes, int n_in,
                              void* d_out, int out_size) {
    const float* x     = (const float*)d_in[0];
    const float* psi0  = (const float*)d_in[1];
    const float* psi1  = (const float*)d_in[2];
    const float* phi   = (const float*)d_in[3];
    const float* gamma = (const float*)d_in[4];
    const float* beta  = (const float*)d_in[5];
    const float* W     = (const float*)d_in[6];
    const float* bias  = (const float*)d_in[7];
    float* out = (float*)d_out;

    k4_init<<<1,        640 >>>(bias, out);
    k1_xf  <<<192,      T256>>>(x, phi);
    k2_u0f <<<384,      T128>>>(psi0, phi);
    k3_p16 <<<192 * 9,  T128>>>(psi1, phi);
    k4_gemv<<<64 * 9,   T256>>>(gamma, beta, W, out);
}

// round 5
// speedup vs baseline: 5.5169x; 1.0780x over previous
#include <cuda_runtime.h>
#include <math.h>

#define T256 256
#define T128 128

// ---------------- global scratch (static, no allocation) ----------------
static __device__ float  g_feat[64 * 243 * 64];   // (b*3+c)*81*64 + ch*64 + pix
static __device__ float2 g_xf  [192 * 1024];      // fft2(x) per (b,c)
static __device__ float2 g_u0f [1536 * 1024];     // fft2(|ifft2(xf*psi0)|) per (bc,t1)

__device__ __forceinline__ int brevn(int i, int bits) {
    return (int)(__brev((unsigned)i) >> (32 - bits));
}

// ---------------- serial register-resident radix-2 DIF FFT ----------------
// natural-order input in v[], output v[i] = X[bitrev(i)] (store with brevn).
// tw[j] = cis(+2*pi*j/N). INV=true: e^{+i}, unscaled. INV=false: e^{-i}.
template<int N, bool INV>
__device__ __forceinline__ void fft_serial(float2* v, const float2* __restrict__ tw) {
#pragma unroll
    for (int m = N; m >= 2; m >>= 1) {
        const int half = m >> 1, step = N / m;
#pragma unroll
        for (int k0 = 0; k0 < N; k0 += m) {
#pragma unroll
            for (int j = 0; j < half; j++) {
                const int lo = k0 + j, hi = lo + half;
                const float2 a = v[lo], b = v[hi];
                const float2 d = make_float2(a.x - b.x, a.y - b.y);
                v[lo] = make_float2(a.x + b.x, a.y + b.y);
                if (j == 0) {
                    v[hi] = d;
                } else if (j * step == N / 4) {
                    v[hi] = INV ? make_float2(-d.y, d.x) : make_float2(d.y, -d.x);
                } else {
                    const float2 w = tw[j * step];
                    const float ws = INV ? w.y : -w.y;
                    v[hi] = make_float2(d.x * w.x - d.y * ws, d.y * w.x + d.x * ws);
                }
            }
        }
    }
}

// ---------------- k1 helpers (register-blocked direct DFT, small kernel) ----------------
__device__ __forceinline__ void fwd_rows_real32(const float* __restrict__ in, float2* __restrict__ out,
                                                const float2* __restrict__ tw) {
    const int lane = threadIdx.x & 31, warp = threadIdx.x >> 5;
    float ar[4] = {0,0,0,0}, ai[4] = {0,0,0,0};
#pragma unroll
    for (int n = 0; n < 32; n++) {
        const float2 w = tw[(lane * n) & 31];
#pragma unroll
        for (int i = 0; i < 4; i++) {
            const float v = in[(warp + 8 * i) * 32 + n];
            ar[i] = fmaf(v,  w.x, ar[i]);
            ai[i] = fmaf(v, -w.y, ai[i]);
        }
    }
#pragma unroll
    for (int i = 0; i < 4; i++) out[(warp + 8 * i) * 32 + lane] = make_float2(ar[i], ai[i]);
}

__device__ __forceinline__ void fwd_cols32(const float2* __restrict__ in, float2* __restrict__ out,
                                           const float2* __restrict__ tw) {
    const int lane = threadIdx.x & 31, warp = threadIdx.x >> 5;
    float ar[4] = {0,0,0,0}, ai[4] = {0,0,0,0};
#pragma unroll
    for (int m = 0; m < 32; m++) {
        const float2 v = in[m * 32 + lane];
#pragma unroll
        for (int i = 0; i < 4; i++) {
            const float2 w = tw[((warp + 8 * i) * m) & 31];
            ar[i] = fmaf(v.x, w.x, fmaf( v.y, w.y, ar[i]));
            ai[i] = fmaf(v.y, w.x, fmaf(-v.x, w.y, ai[i]));
        }
    }
#pragma unroll
    for (int i = 0; i < 4; i++) out[(warp + 8 * i) * 32 + lane] = make_float2(ar[i], ai[i]);
}

__device__ __forceinline__ void p8_from32(const float2* __restrict__ S, const float* __restrict__ PHI,
                                          float2* __restrict__ P8) {
    const int tid = threadIdx.x;
    if (tid < 64) {
        const int u = tid >> 3, v = tid & 7;
        float ar = 0.f, ai = 0.f;
#pragma unroll
        for (int i = 0; i < 4; i++)
#pragma unroll
            for (int j = 0; j < 4; j++) {
                const int off = (8 * i + u) * 32 + 8 * j + v;
                const float p = PHI[off];
                const float2 z = S[off];
                ar = fmaf(z.x, p, ar); ai = fmaf(z.y, p, ai);
            }
        P8[tid] = make_float2(ar * 0.0625f, ai * 0.0625f);
    }
}

__device__ __forceinline__ void ifft8_store64(const float2* __restrict__ P8, const float2* __restrict__ tw8,
                                              float* __restrict__ dst) {
    const int tid = threadIdx.x;
    if (tid < 64) {
        const int y = tid >> 3, xx = tid & 7;
        float acc = 0.f;
#pragma unroll
        for (int u = 0; u < 8; u++)
#pragma unroll
            for (int v = 0; v < 8; v++) {
                const int ph = (y * u + xx * v) & 7;
                const float2 p = P8[u * 8 + v];
                const float2 w = tw8[ph];
                acc = fmaf(p.x, w.x, fmaf(-p.y, w.y, acc));
            }
        dst[tid] = acc * (1.0f / 64.0f);
    }
}

// ---------------- K1: xf = fft2(x); s0 ----------------
__global__ void __launch_bounds__(T256)
k1_xf(const float* __restrict__ x, const float* __restrict__ phi) {
    __shared__ float  U[1024];
    __shared__ float2 Z[1024];
    __shared__ float2 XF[1024];
    __shared__ float  PHI[1024];
    __shared__ float2 P8[64];
    __shared__ float2 tw32[32];
    __shared__ float2 tw8[8];
    const int tid = threadIdx.x, bc = blockIdx.x;

    if (tid < 32) { float s, c; sincospif((float)tid * (1.0f / 16.0f), &s, &c); tw32[tid] = make_float2(c, s); }
    else if (tid < 40) { const int j = tid - 32; float s, c; sincospif((float)j * 0.25f, &s, &c); tw8[j] = make_float2(c, s); }
    for (int i = tid; i < 1024; i += T256) { U[i] = x[bc * 1024 + i]; PHI[i] = phi[i]; }
    __syncthreads();

    fwd_rows_real32(U, Z, tw32);
    __syncthreads();
    fwd_cols32(Z, XF, tw32);
    __syncthreads();

    float2* dst = g_xf + bc * 1024;
    for (int i = tid; i < 1024; i += T256) dst[i] = XF[i];

    p8_from32(XF, PHI, P8);
    __syncthreads();
    ifft8_store64(P8, tw8, g_feat + bc * 81 * 64);
}

// ---------------- K2: u0f per (bc, t1); s1a — forward-packed pairs ----------------
__global__ void __launch_bounds__(T128)
k2_u0f(const float* __restrict__ psi0, const float* __restrict__ phi) {
    __shared__ float2 XF[32 * 33];
    __shared__ float2 ZW[4][32 * 33];   // per-warp inverse work; ZW[0..1] reused as packed buffers
    __shared__ float  PHI[1024];
    __shared__ float2 P8s[2][64];
    __shared__ float2 R8s[2][64];
    __shared__ float2 tw32[32];
    __shared__ float2 tw8[8];
    const int tid = threadIdx.x;
    const int bc = blockIdx.x >> 1, half = blockIdx.x & 1;
    const int w = tid >> 5, lane = tid & 31;
    const int t1 = half * 4 + w;

    if (tid < 32) { float s, c; sincospif((float)tid * (1.0f / 16.0f), &s, &c); tw32[tid] = make_float2(c, s); }
    else if (tid < 40) { const int j = tid - 32; float s, c; sincospif((float)j * 0.25f, &s, &c); tw8[j] = make_float2(c, s); }

    const float2* xf = g_xf + bc * 1024;
    for (int i = tid; i < 1024; i += T128) {
        XF[(i >> 5) * 33 + (i & 31)] = xf[i];
        PHI[i] = phi[i];
    }
    __syncthreads();

    float2 v[32];
    // inverse rows on xf * psi0[t1]
    {
        const float* ps = psi0 + t1 * 1024 + lane * 32;
#pragma unroll
        for (int n = 0; n < 32; n++) {
            const float p = ps[n];
            const float2 z = XF[lane * 33 + n];
            v[n] = make_float2(z.x * p, z.y * p);
        }
    }
    fft_serial<32, true>(v, tw32);
#pragma unroll
    for (int n = 0; n < 32; n++) ZW[w][lane * 33 + brevn(n, 5)] = v[n];
    __syncthreads();

    // inverse cols + modulus -> u kept in registers (v[m].x)
#pragma unroll
    for (int m = 0; m < 32; m++) v[m] = ZW[w][m * 33 + lane];
    fft_serial<32, true>(v, tw32);
#pragma unroll
    for (int m = 0; m < 32; m++)
        v[m].x = sqrtf(v[m].x * v[m].x + v[m].y * v[m].y) * (1.0f / 1024.0f);
    __syncthreads();   // all inverse reads done before packed overwrite of ZW[0..1]

    // packed write: pair p = w>>1, component = w&1
    {
        float* dstf = (float*)ZW[w >> 1];
        const int comp = w & 1;
#pragma unroll
        for (int m = 0; m < 32; m++)
            dstf[(brevn(m, 5) * 33 + lane) * 2 + comp] = v[m].x;
    }
    __syncthreads();

    // forward rows on packed u (64 lines: p=tid>>5, ln=tid&31)
    if (tid < 64) {
        const int p = tid >> 5, ln = tid & 31;
#pragma unroll
        for (int n = 0; n < 32; n++) v[n] = ZW[p][ln * 33 + n];
        fft_serial<32, false>(v, tw32);
#pragma unroll
        for (int n = 0; n < 32; n++) ZW[p][ln * 33 + brevn(n, 5)] = v[n];
    }
    __syncthreads();

    // forward cols (packed) -> natural order spectrum Z
    if (tid < 64) {
        const int p = tid >> 5, ln = tid & 31;
#pragma unroll
        for (int m = 0; m < 32; m++) v[m] = ZW[p][m * 33 + ln];
        fft_serial<32, false>(v, tw32);
#pragma unroll
        for (int m = 0; m < 32; m++) ZW[p][brevn(m, 5) * 33 + ln] = v[m];
    }
    __syncthreads();

    // unpack via conjugate symmetry, store both u0f spectra
    if (tid < 64) {
        const int p = tid >> 5, ln = tid & 31;
        const int lnn = (32 - ln) & 31;
        float2* dstA = g_u0f + (bc * 8 + half * 4 + 2 * p) * 1024;
        float2* dstB = dstA + 1024;
#pragma unroll
        for (int m = 0; m < 32; m++) {
            const float2 z1 = ZW[p][m * 33 + ln];
            const float2 z2 = ZW[p][(((32 - m) & 31)) * 33 + lnn];
            dstA[m * 32 + ln] = make_float2(0.5f * (z1.x + z2.x), 0.5f * (z1.y - z2.y));
            dstB[m * 32 + ln] = make_float2(0.5f * (z1.y + z2.y), 0.5f * (z2.x - z1.x));
        }
    }
    __syncthreads();

    // s1a packed: p8 = sub4(Z*phi), one point per thread (2 pairs x 64)
    {
        const int pp = tid >> 6, o = tid & 63;
        const int u = o >> 3, vv = o & 7;
        float ar = 0.f, ai = 0.f;
#pragma unroll
        for (int i = 0; i < 4; i++)
#pragma unroll
            for (int j = 0; j < 4; j++) {
                const float p = PHI[(8 * i + u) * 32 + 8 * j + vv];
                const float2 z = ZW[pp][(8 * i + u) * 33 + 8 * j + vv];
                ar = fmaf(z.x, p, ar); ai = fmaf(z.y, p, ai);
            }
        P8s[pp][o] = make_float2(ar * 0.0625f, ai * 0.0625f);
    }
    __syncthreads();

    // separable complex ifft8: row pass
    {
        const int pp = tid >> 6, o = tid & 63;
        const int y = o >> 3, vv = o & 7;
        float ar = 0.f, ai = 0.f;
#pragma unroll
        for (int u = 0; u < 8; u++) {
            const float2 p = P8s[pp][u * 8 + vv];
            const float2 w8 = tw8[(y * u) & 7];
            ar = fmaf(p.x, w8.x, fmaf(-p.y, w8.y, ar));
            ai = fmaf(p.y, w8.x, fmaf( p.x, w8.y, ai));
        }
        R8s[pp][o] = make_float2(ar, ai);
    }
    __syncthreads();

    // col pass: Re -> even tile, Im -> odd tile
    {
        const int pp = tid >> 6, o = tid & 63;
        const int y = o >> 3, xx = o & 7;
        float ar = 0.f, ai = 0.f;
#pragma unroll
        for (int vv = 0; vv < 8; vv++) {
            const float2 p = R8s[pp][y * 8 + vv];
            const float2 w8 = tw8[(xx * vv) & 7];
            ar = fmaf(p.x, w8.x, fmaf(-p.y, w8.y, ar));
            ai = fmaf(p.y, w8.x, fmaf( p.x, w8.y, ai));
        }
        float* fb = g_feat + bc * 81 * 64 + (1 + half * 4 + 2 * pp) * 64;
        fb[o]      = ar * (1.0f / 64.0f);
        fb[64 + o] = ai * (1.0f / 64.0f);
    }
}

// ---------------- K3: 8 t2 tiles per (bc, src) block, forward-packed pairs ----------------
// grid = 192*9: role 0 -> src=xf (s1b), role r=1..8 -> src=u0f[r-1] (s2 row).
__global__ void __launch_bounds__(T128)
k3_p16(const float* __restrict__ psi1, const float* __restrict__ phi) {
    __shared__ float2 SRC[1024];
    __shared__ float2 Q[8][16 * 17];     // per-tile spectra (inverse side)
    __shared__ float2 UP[4][16 * 17];    // packed forward work
    __shared__ float  PHI1[256];
    __shared__ float2 P8s[4][64];
    __shared__ float2 R8s[4][64];
    __shared__ float2 tw16[16];
    __shared__ float2 tw8[8];
    const int tid = threadIdx.x;
    const int bc = blockIdx.x / 9;
    const int role = blockIdx.x - bc * 9;

    const float2* src = (role == 0) ? (g_xf + bc * 1024) : (g_u0f + (bc * 8 + role - 1) * 1024);
    const int chbase = (role == 0) ? 9 : 17 + (role - 1) * 8;

    if (tid < 16) { float s, c; sincospif((float)tid * 0.125f, &s, &c); tw16[tid] = make_float2(c, s); }
    else if (tid < 24) { const int j = tid - 16; float s, c; sincospif((float)j * 0.25f, &s, &c); tw8[j] = make_float2(c, s); }

    for (int i = tid; i < 1024; i += T128) SRC[i] = src[i];
#pragma unroll
    for (int k = 0; k < 2; k++) {
        const int idx = tid + 128 * k;
        const int a = idx >> 4, b2 = idx & 15;
        PHI1[idx] = 0.25f * (phi[a * 32 + b2] + phi[(a + 16) * 32 + b2] +
                             phi[a * 32 + b2 + 16] + phi[(a + 16) * 32 + b2 + 16]);
    }
    __syncthreads();

    // Stage A (reordered): fix output position, load SRC once, loop psi tiles
#pragma unroll
    for (int k = 0; k < 2; k++) {
        const int e = tid + 128 * k;          // 0..255
        const int a = e >> 4, b2 = e & 15;
        const int o00 = a * 32 + b2;
        const float2 z00 = SRC[o00],       z01 = SRC[o00 + 16];
        const float2 z10 = SRC[o00 + 512], z11 = SRC[o00 + 528];
#pragma unroll
        for (int t = 0; t < 8; t++) {
            const float* ps = psi1 + t * 1024;
            const float p00 = ps[o00],       p01 = ps[o00 + 16];
            const float p10 = ps[o00 + 512], p11 = ps[o00 + 528];
            float ar = fmaf(z00.x, p00, fmaf(z01.x, p01, fmaf(z10.x, p10, z11.x * p11)));
            float ai = fmaf(z00.y, p00, fmaf(z01.y, p01, fmaf(z10.y, p10, z11.y * p11)));
            Q[t][a * 17 + b2] = make_float2(0.25f * ar, 0.25f * ai);
        }
    }
    __syncthreads();

    float2 v[16];
    const int tile = tid >> 4, ln = tid & 15;

    // Stage B: rows inverse (per tile)
#pragma unroll
    for (int n = 0; n < 16; n++) v[n] = Q[tile][ln * 17 + n];
    fft_serial<16, true>(v, tw16);
#pragma unroll
    for (int n = 0; n < 16; n++) Q[tile][ln * 17 + brevn(n, 4)] = v[n];
    __syncthreads();

    // Stage C: cols inverse + modulus, packed store into UP (component tile&1)
#pragma unroll
    for (int m = 0; m < 16; m++) v[m] = Q[tile][m * 17 + ln];
    fft_serial<16, true>(v, tw16);
    {
        float* upf = (float*)UP[tile >> 1];
        const int comp = tile & 1;
#pragma unroll
        for (int m = 0; m < 16; m++) {
            const float u = sqrtf(v[m].x * v[m].x + v[m].y * v[m].y) * (1.0f / 256.0f);
            upf[(brevn(m, 4) * 17 + ln) * 2 + comp] = u;
        }
    }
    __syncthreads();

    // Stage D: rows fwd on packed u (4 pairs x 16 lines = 64 lines)
    if (tid < 64) {
        const int p = tid >> 4, l2 = tid & 15;
#pragma unroll
        for (int n = 0; n < 16; n++) v[n] = UP[p][l2 * 17 + n];
        fft_serial<16, false>(v, tw16);
#pragma unroll
        for (int n = 0; n < 16; n++) UP[p][l2 * 17 + brevn(n, 4)] = v[n];
    }
    __syncthreads();

    // Stage E: cols fwd (packed) -> natural-order packed spectrum
    if (tid < 64) {
        const int p = tid >> 4, l2 = tid & 15;
#pragma unroll
        for (int m = 0; m < 16; m++) v[m] = UP[p][m * 17 + l2];
        fft_serial<16, false>(v, tw16);
#pragma unroll
        for (int m = 0; m < 16; m++) UP[p][brevn(m, 4) * 17 + l2] = v[m];
    }
    __syncthreads();

    // Stage F: p8 = sub2(Zpacked * phi1), 4 pairs x 64 points
#pragma unroll
    for (int k = 0; k < 2; k++) {
        const int idx = tid + 128 * k;
        const int pp = idx >> 6, o = idx & 63;
        const int u = o >> 3, vv = o & 7;
        float ar = 0.f, ai = 0.f;
#pragma unroll
        for (int i = 0; i < 2; i++)
#pragma unroll
            for (int j = 0; j < 2; j++) {
                const float p = PHI1[(8 * i + u) * 16 + 8 * j + vv];
                const float2 z = UP[pp][(8 * i + u) * 17 + 8 * j + vv];
                ar = fmaf(z.x, p, ar); ai = fmaf(z.y, p, ai);
            }
        P8s[pp][o] = make_float2(0.25f * ar, 0.25f * ai);
    }
    __syncthreads();

    // Stage G1: separable ifft8 — row pass
#pragma unroll
    for (int k = 0; k < 2; k++) {
        const int idx = tid + 128 * k;
        const int pp = idx >> 6, o = idx & 63;
        const int y = o >> 3, vv = o & 7;
        float ar = 0.f, ai = 0.f;
#pragma unroll
        for (int u = 0; u < 8; u++) {
            const float2 p = P8s[pp][u * 8 + vv];
            const float2 w8 = tw8[(y * u) & 7];
            ar = fmaf(p.x, w8.x, fmaf(-p.y, w8.y, ar));
            ai = fmaf(p.y, w8.x, fmaf( p.x, w8.y, ai));
        }
        R8s[pp][o] = make_float2(ar, ai);
    }
    __syncthreads();

    // Stage G2: col pass; Re -> even tile channel, Im -> odd tile channel
    float* fb = g_feat + bc * 81 * 64;
#pragma unroll
    for (int k = 0; k < 2; k++) {
        const int idx = tid + 128 * k;
        const int pp = idx >> 6, o = idx & 63;
        const int y = o >> 3, xx = o & 7;
        float ar = 0.f, ai = 0.f;
#pragma unroll
        for (int vv = 0; vv < 8; vv++) {
            const float2 p = R8s[pp][y * 8 + vv];
            const float2 w8 = tw8[(xx * vv) & 7];
            ar = fmaf(p.x, w8.x, fmaf(-p.y, w8.y, ar));
            ai = fmaf(p.y, w8.x, fmaf( p.x, w8.y, ai));
        }
        fb[(chbase + 2 * pp)     * 64 + o] = ar * (1.0f / 64.0f);
        fb[(chbase + 2 * pp + 1) * 64 + o] = ai * (1.0f / 64.0f);
    }
}

// ---------------- K4: init + fused stats/GEMV with atomic finish ----------------
__global__ void __launch_bounds__(640)
k4_init(const float* __restrict__ bias, float* __restrict__ out) {
    const int t = threadIdx.x;
    if (t < 640) out[t] = bias[t % 10];
}

__global__ void __launch_bounds__(T256)
k4_gemv(const float* __restrict__ gamma, const float* __restrict__ beta,
        const float* __restrict__ W, float* __restrict__ out) {
    const int b = blockIdx.x / 9, c = blockIdx.x - (blockIdx.x / 9) * 9;
    const float* f = g_feat + b * 15552 + c * 1728;   // 3 complete groups of 576
    __shared__ float smu[3], srs[3];
    __shared__ float redA[3][2], redB[3][2];
    const int tid = threadIdx.x;

    if (tid < 192) {
        const int g = tid >> 6, l = tid & 63;
        float s = 0.f, s2 = 0.f;
#pragma unroll
        for (int i = l; i < 576; i += 64) {
            const float xv = f[g * 576 + i];
            s += xv; s2 = fmaf(xv, xv, s2);
        }
#pragma unroll
        for (int o = 16; o > 0; o >>= 1) {
            s  += __shfl_xor_sync(0xffffffffu, s,  o);
            s2 += __shfl_xor_sync(0xffffffffu, s2, o);
        }
        if ((l & 31) == 0) { redA[g][l >> 5] = s; redB[g][l >> 5] = s2; }
    }
    __syncthreads();
    if (tid < 3) {
        const float s = redA[tid][0] + redA[tid][1];
        const float s2 = redB[tid][0] + redB[tid][1];
        const float m = s * (1.0f / 576.0f);
        smu[tid] = m;
        srs[tid] = rsqrtf(s2 * (1.0f / 576.0f) - m * m + 1e-5f);
    }
    __syncthreads();

    float acc[10];
#pragma unroll
    for (int j = 0; j < 10; j++) acc[j] = 0.f;
    const float* Wc = W + c * 1728;
    for (int i = tid; i < 1728; i += T256) {
        const int l = i >> 6;
        const int gl = l / 9;
        const int ch = c * 27 + l;
        const float nv = (f[i] - smu[gl]) * srs[gl] * gamma[ch] + beta[ch];
#pragma unroll
        for (int j = 0; j < 10; j++)
            acc[j] = fmaf(nv, Wc[j * 15552 + i], acc[j]);
    }

    __shared__ float red[8][10];
    const int lane = tid & 31, wrp = tid >> 5;
#pragma unroll
    for (int j = 0; j < 10; j++) {
        float vv = acc[j];
#pragma unroll
        for (int o = 16; o > 0; o >>= 1) vv += __shfl_xor_sync(0xffffffffu, vv, o);
        if (lane == 0) red[wrp][j] = vv;
    }
    __syncthreads();
    if (tid < 10) {
        float vv = 0.f;
#pragma unroll
        for (int w = 0; w < 8; w++) vv += red[w][tid];
        atomicAdd(&out[b * 10 + tid], vv);
    }
}

// ---------------- launch ----------------
extern "C" void kernel_launch(void* const* d_in, const int* in_sizes, int n_in,
                              void* d_out, int out_size) {
    const float* x     = (const float*)d_in[0];
    const float* psi0  = (const float*)d_in[1];
    const float* psi1  = (const float*)d_in[2];
    const float* phi   = (const float*)d_in[3];
    const float* gamma = (const float*)d_in[4];
    const float* beta  = (const float*)d_in[5];
    const float* W     = (const float*)d_in[6];
    const float* bias  = (const float*)d_in[7];
    float* out = (float*)d_out;

    k4_init<<<1,        640 >>>(bias, out);
    k1_xf  <<<192,      T256>>>(x, phi);
    k2_u0f <<<384,      T128>>>(psi0, phi);
    k3_p16 <<<192 * 9,  T128>>>(psi1, phi);
    k4_gemv<<<64 * 9,   T256>>>(gamma, beta, W, out);
}

// round 6
// speedup vs baseline: 5.9542x; 1.0793x over previous
#include <cuda_runtime.h>
#include <math.h>

#define T256 256
#define T128 128

// ---------------- global scratch (static, no allocation) ----------------
static __device__ float  g_feat[64 * 243 * 64];   // (b*3+c)*81*64 + ch*64 + pix
static __device__ float2 g_xf  [192 * 1024];      // fft2(x) per (b,c)
static __device__ float2 g_u0f [1536 * 1024];     // fft2(|ifft2(xf*psi0)|) per (bc,t1)

__device__ __forceinline__ int brevn(int i, int bits) {
    return (int)(__brev((unsigned)i) >> (32 - bits));
}

// ---------------- serial register-resident radix-2 DIF FFT ----------------
template<int N, bool INV>
__device__ __forceinline__ void fft_serial(float2* v, const float2* __restrict__ tw) {
#pragma unroll
    for (int m = N; m >= 2; m >>= 1) {
        const int half = m >> 1, step = N / m;
#pragma unroll
        for (int k0 = 0; k0 < N; k0 += m) {
#pragma unroll
            for (int j = 0; j < half; j++) {
                const int lo = k0 + j, hi = lo + half;
                const float2 a = v[lo], b = v[hi];
                const float2 d = make_float2(a.x - b.x, a.y - b.y);
                v[lo] = make_float2(a.x + b.x, a.y + b.y);
                if (j == 0) {
                    v[hi] = d;
                } else if (j * step == N / 4) {
                    v[hi] = INV ? make_float2(-d.y, d.x) : make_float2(d.y, -d.x);
                } else {
                    const float2 w = tw[j * step];
                    const float ws = INV ? w.y : -w.y;
                    v[hi] = make_float2(d.x * w.x - d.y * ws, d.y * w.x + d.x * ws);
                }
            }
        }
    }
}

// ---------------- k1 helpers (register-blocked direct DFT, small kernel) ----------------
__device__ __forceinline__ void fwd_rows_real32(const float* __restrict__ in, float2* __restrict__ out,
                                                const float2* __restrict__ tw) {
    const int lane = threadIdx.x & 31, warp = threadIdx.x >> 5;
    float ar[4] = {0,0,0,0}, ai[4] = {0,0,0,0};
#pragma unroll
    for (int n = 0; n < 32; n++) {
        const float2 w = tw[(lane * n) & 31];
#pragma unroll
        for (int i = 0; i < 4; i++) {
            const float v = in[(warp + 8 * i) * 32 + n];
            ar[i] = fmaf(v,  w.x, ar[i]);
            ai[i] = fmaf(v, -w.y, ai[i]);
        }
    }
#pragma unroll
    for (int i = 0; i < 4; i++) out[(warp + 8 * i) * 32 + lane] = make_float2(ar[i], ai[i]);
}

__device__ __forceinline__ void fwd_cols32(const float2* __restrict__ in, float2* __restrict__ out,
                                           const float2* __restrict__ tw) {
    const int lane = threadIdx.x & 31, warp = threadIdx.x >> 5;
    float ar[4] = {0,0,0,0}, ai[4] = {0,0,0,0};
#pragma unroll
    for (int m = 0; m < 32; m++) {
        const float2 v = in[m * 32 + lane];
#pragma unroll
        for (int i = 0; i < 4; i++) {
            const float2 w = tw[((warp + 8 * i) * m) & 31];
            ar[i] = fmaf(v.x, w.x, fmaf( v.y, w.y, ar[i]));
            ai[i] = fmaf(v.y, w.x, fmaf(-v.x, w.y, ai[i]));
        }
    }
#pragma unroll
    for (int i = 0; i < 4; i++) out[(warp + 8 * i) * 32 + lane] = make_float2(ar[i], ai[i]);
}

__device__ __forceinline__ void p8_from32(const float2* __restrict__ S, const float* __restrict__ PHI,
                                          float2* __restrict__ P8) {
    const int tid = threadIdx.x;
    if (tid < 64) {
        const int u = tid >> 3, v = tid & 7;
        float ar = 0.f, ai = 0.f;
#pragma unroll
        for (int i = 0; i < 4; i++)
#pragma unroll
            for (int j = 0; j < 4; j++) {
                const int off = (8 * i + u) * 32 + 8 * j + v;
                const float p = PHI[off];
                const float2 z = S[off];
                ar = fmaf(z.x, p, ar); ai = fmaf(z.y, p, ai);
            }
        P8[tid] = make_float2(ar * 0.0625f, ai * 0.0625f);
    }
}

__device__ __forceinline__ void ifft8_store64(const float2* __restrict__ P8, const float2* __restrict__ tw8,
                                              float* __restrict__ dst) {
    const int tid = threadIdx.x;
    if (tid < 64) {
        const int y = tid >> 3, xx = tid & 7;
        float acc = 0.f;
#pragma unroll
        for (int u = 0; u < 8; u++)
#pragma unroll
            for (int v = 0; v < 8; v++) {
                const int ph = (y * u + xx * v) & 7;
                const float2 p = P8[u * 8 + v];
                const float2 w = tw8[ph];
                acc = fmaf(p.x, w.x, fmaf(-p.y, w.y, acc));
            }
        dst[tid] = acc * (1.0f / 64.0f);
    }
}

// ---------------- K1: xf = fft2(x); s0 ----------------
__global__ void __launch_bounds__(T256)
k1_xf(const float* __restrict__ x, const float* __restrict__ phi) {
    __shared__ float  U[1024];
    __shared__ float2 Z[1024];
    __shared__ float2 XF[1024];
    __shared__ float  PHI[1024];
    __shared__ float2 P8[64];
    __shared__ float2 tw32[32];
    __shared__ float2 tw8[8];
    const int tid = threadIdx.x, bc = blockIdx.x;

    if (tid < 32) { float s, c; sincospif((float)tid * (1.0f / 16.0f), &s, &c); tw32[tid] = make_float2(c, s); }
    else if (tid < 40) { const int j = tid - 32; float s, c; sincospif((float)j * 0.25f, &s, &c); tw8[j] = make_float2(c, s); }
    for (int i = tid; i < 1024; i += T256) { U[i] = x[bc * 1024 + i]; PHI[i] = phi[i]; }
    __syncthreads();

    fwd_rows_real32(U, Z, tw32);
    __syncthreads();
    fwd_cols32(Z, XF, tw32);
    __syncthreads();

    float2* dst = g_xf + bc * 1024;
    for (int i = tid; i < 1024; i += T256) dst[i] = XF[i];

    p8_from32(XF, PHI, P8);
    __syncthreads();
    ifft8_store64(P8, tw8, g_feat + bc * 81 * 64);
}

// ---------------- K2: u0f per (bc, t1); s1a — forward-packed pairs ----------------
__global__ void __launch_bounds__(T128)
k2_u0f(const float* __restrict__ psi0, const float* __restrict__ phi) {
    __shared__ float2 XF[32 * 33];
    __shared__ float2 ZW[4][32 * 33];   // per-warp inverse work; ZW[0..1] reused as packed buffers
    __shared__ float  PHI[1024];
    __shared__ float2 P8s[2][64];
    __shared__ float2 R8s[2][64];
    __shared__ float2 tw32[32];
    __shared__ float2 tw8[8];
    const int tid = threadIdx.x;
    const int bc = blockIdx.x >> 1, half = blockIdx.x & 1;
    const int w = tid >> 5, lane = tid & 31;
    const int t1 = half * 4 + w;

    if (tid < 32) { float s, c; sincospif((float)tid * (1.0f / 16.0f), &s, &c); tw32[tid] = make_float2(c, s); }
    else if (tid < 40) { const int j = tid - 32; float s, c; sincospif((float)j * 0.25f, &s, &c); tw8[j] = make_float2(c, s); }

    const float2* xf = g_xf + bc * 1024;
    for (int i = tid; i < 1024; i += T128) {
        XF[(i >> 5) * 33 + (i & 31)] = xf[i];
        PHI[i] = phi[i];
    }
    __syncthreads();

    float2 v[32];
    // inverse rows on xf * psi0[t1]
    {
        const float* ps = psi0 + t1 * 1024 + lane * 32;
#pragma unroll
        for (int n = 0; n < 32; n++) {
            const float p = ps[n];
            const float2 z = XF[lane * 33 + n];
            v[n] = make_float2(z.x * p, z.y * p);
        }
    }
    fft_serial<32, true>(v, tw32);
#pragma unroll
    for (int n = 0; n < 32; n++) ZW[w][lane * 33 + brevn(n, 5)] = v[n];
    __syncthreads();

    // inverse cols + modulus -> u kept in registers (v[m].x)
#pragma unroll
    for (int m = 0; m < 32; m++) v[m] = ZW[w][m * 33 + lane];
    fft_serial<32, true>(v, tw32);
#pragma unroll
    for (int m = 0; m < 32; m++)
        v[m].x = sqrtf(v[m].x * v[m].x + v[m].y * v[m].y) * (1.0f / 1024.0f);
    __syncthreads();   // all inverse reads done before packed overwrite of ZW[0..1]

    // packed write: pair p = w>>1, component = w&1
    {
        float* dstf = (float*)ZW[w >> 1];
        const int comp = w & 1;
#pragma unroll
        for (int m = 0; m < 32; m++)
            dstf[(brevn(m, 5) * 33 + lane) * 2 + comp] = v[m].x;
    }
    __syncthreads();

    // forward rows on packed u (64 lines: p=tid>>5, ln=tid&31)
    if (tid < 64) {
        const int p = tid >> 5, ln = tid & 31;
#pragma unroll
        for (int n = 0; n < 32; n++) v[n] = ZW[p][ln * 33 + n];
        fft_serial<32, false>(v, tw32);
#pragma unroll
        for (int n = 0; n < 32; n++) ZW[p][ln * 33 + brevn(n, 5)] = v[n];
    }
    __syncthreads();

    // forward cols (packed) -> natural order spectrum Z
    if (tid < 64) {
        const int p = tid >> 5, ln = tid & 31;
#pragma unroll
        for (int m = 0; m < 32; m++) v[m] = ZW[p][m * 33 + ln];
        fft_serial<32, false>(v, tw32);
#pragma unroll
        for (int m = 0; m < 32; m++) ZW[p][brevn(m, 5) * 33 + ln] = v[m];
    }
    __syncthreads();

    // unpack via conjugate symmetry, store both u0f spectra
    if (tid < 64) {
        const int p = tid >> 5, ln = tid & 31;
        const int lnn = (32 - ln) & 31;
        float2* dstA = g_u0f + (bc * 8 + half * 4 + 2 * p) * 1024;
        float2* dstB = dstA + 1024;
#pragma unroll
        for (int m = 0; m < 32; m++) {
            const float2 z1 = ZW[p][m * 33 + ln];
            const float2 z2 = ZW[p][(((32 - m) & 31)) * 33 + lnn];
            dstA[m * 32 + ln] = make_float2(0.5f * (z1.x + z2.x), 0.5f * (z1.y - z2.y));
            dstB[m * 32 + ln] = make_float2(0.5f * (z1.y + z2.y), 0.5f * (z2.x - z1.x));
        }
    }
    __syncthreads();

    // s1a packed: p8 = sub4(Z*phi), one point per thread (2 pairs x 64)
    {
        const int pp = tid >> 6, o = tid & 63;
        const int u = o >> 3, vv = o & 7;
        float ar = 0.f, ai = 0.f;
#pragma unroll
        for (int i = 0; i < 4; i++)
#pragma unroll
            for (int j = 0; j < 4; j++) {
                const float p = PHI[(8 * i + u) * 32 + 8 * j + vv];
                const float2 z = ZW[pp][(8 * i + u) * 33 + 8 * j + vv];
                ar = fmaf(z.x, p, ar); ai = fmaf(z.y, p, ai);
            }
        P8s[pp][o] = make_float2(ar * 0.0625f, ai * 0.0625f);
    }
    __syncthreads();

    // separable complex ifft8: row pass
    {
        const int pp = tid >> 6, o = tid & 63;
        const int y = o >> 3, vv = o & 7;
        float ar = 0.f, ai = 0.f;
#pragma unroll
        for (int u = 0; u < 8; u++) {
            const float2 p = P8s[pp][u * 8 + vv];
            const float2 w8 = tw8[(y * u) & 7];
            ar = fmaf(p.x, w8.x, fmaf(-p.y, w8.y, ar));
            ai = fmaf(p.y, w8.x, fmaf( p.x, w8.y, ai));
        }
        R8s[pp][o] = make_float2(ar, ai);
    }
    __syncthreads();

    // col pass: Re -> even tile, Im -> odd tile
    {
        const int pp = tid >> 6, o = tid & 63;
        const int y = o >> 3, xx = o & 7;
        float ar = 0.f, ai = 0.f;
#pragma unroll
        for (int vv = 0; vv < 8; vv++) {
            const float2 p = R8s[pp][y * 8 + vv];
            const float2 w8 = tw8[(xx * vv) & 7];
            ar = fmaf(p.x, w8.x, fmaf(-p.y, w8.y, ar));
            ai = fmaf(p.y, w8.x, fmaf( p.x, w8.y, ai));
        }
        float* fb = g_feat + bc * 81 * 64 + (1 + half * 4 + 2 * pp) * 64;
        fb[o]      = ar * (1.0f / 64.0f);
        fb[64 + o] = ai * (1.0f / 64.0f);
    }
}

// ---------------- K3: warp-decomposed P16 pipelines (one block barrier) ----------------
// grid = 192*9: role 0 -> src=xf (s1b), role r=1..8 -> src=u0f[r-1] (s2 row).
// Warp w owns tiles {2w, 2w+1}; lane = 32 threads, h = lane>>4 selects tile, ln = lane&15.
// All post-A synchronization is __syncwarp().
__global__ void __launch_bounds__(T128, 6)
k3_p16(const float* __restrict__ psi1, const float* __restrict__ phi) {
    __shared__ float2 Q[8][16 * 17];     // per-tile spectra; Q[2w] aliased as packed UP after stage C
    __shared__ float  PHI1[256];
    __shared__ float2 P8W[4][64];
    __shared__ float2 R8W[4][64];
    __shared__ float2 tw16[16];
    __shared__ float2 tw8[8];
    const int tid = threadIdx.x;
    const int w = tid >> 5, lane = tid & 31;
    const int h = lane >> 4, ln = lane & 15;
    const int bc = blockIdx.x / 9;
    const int role = blockIdx.x - bc * 9;

    const float2* __restrict__ src = (role == 0) ? (g_xf + bc * 1024)
                                                 : (g_u0f + (bc * 8 + role - 1) * 1024);
    const int chbase = (role == 0) ? 9 : 17 + (role - 1) * 8;

    if (tid < 16) { float s, c; sincospif((float)tid * 0.125f, &s, &c); tw16[tid] = make_float2(c, s); }
    else if (tid < 24) { const int j = tid - 16; float s, c; sincospif((float)j * 0.25f, &s, &c); tw8[j] = make_float2(c, s); }

    // PHI1 = sub2(phi), 2 elements per thread
#pragma unroll
    for (int k = 0; k < 2; k++) {
        const int idx = tid + 128 * k;
        const int a = idx >> 4, b2 = idx & 15;
        PHI1[idx] = 0.25f * (phi[a * 32 + b2] + phi[(a + 16) * 32 + b2] +
                             phi[a * 32 + b2 + 16] + phi[(a + 16) * 32 + b2 + 16]);
    }

    // Stage A (block-wide, output-stationary over the 8 psi tiles), SRC read from gmem
#pragma unroll
    for (int k = 0; k < 2; k++) {
        const int e = tid + 128 * k;          // 0..255
        const int a = e >> 4, b2 = e & 15;
        const int o00 = a * 32 + b2;
        const float2 z00 = src[o00],       z01 = src[o00 + 16];
        const float2 z10 = src[o00 + 512], z11 = src[o00 + 528];
#pragma unroll
        for (int t = 0; t < 8; t++) {
            const float* ps = psi1 + t * 1024;
            const float p00 = ps[o00],       p01 = ps[o00 + 16];
            const float p10 = ps[o00 + 512], p11 = ps[o00 + 528];
            float ar = fmaf(z00.x, p00, fmaf(z01.x, p01, fmaf(z10.x, p10, z11.x * p11)));
            float ai = fmaf(z00.y, p00, fmaf(z01.y, p01, fmaf(z10.y, p10, z11.y * p11)));
            Q[t][a * 17 + b2] = make_float2(0.25f * ar, 0.25f * ai);
        }
    }
    __syncthreads();     // the ONLY block barrier: Q + PHI1 visible to all

    float2 v[16];
    const int tb = 2 * w + h;     // this half-warp's tile
    float2* const QT = Q[tb];
    float2* const UPW = Q[2 * w]; // packed buffer aliases the even tile
    float* const upf = (float*)UPW;

    // Stage B: rows inverse (thread owns row ln of tile tb)
#pragma unroll
    for (int n = 0; n < 16; n++) v[n] = QT[ln * 17 + n];
    fft_serial<16, true>(v, tw16);
#pragma unroll
    for (int n = 0; n < 16; n++) QT[ln * 17 + brevn(n, 4)] = v[n];
    __syncwarp();

    // Stage C: cols inverse + modulus; packed write (comp h) into UPW (aliases Q[2w])
#pragma unroll
    for (int m = 0; m < 16; m++) v[m] = QT[m * 17 + ln];
    __syncwarp();        // all reads of Q[2w] complete before packed overwrite
    fft_serial<16, true>(v, tw16);
#pragma unroll
    for (int m = 0; m < 16; m++) {
        const float u = sqrtf(v[m].x * v[m].x + v[m].y * v[m].y) * (1.0f / 256.0f);
        upf[(brevn(m, 4) * 17 + ln) * 2 + h] = u;
    }
    __syncwarp();

    // Stage D: rows fwd on packed u (16 lines; lanes 0-15)
    if (h == 0) {
#pragma unroll
        for (int n = 0; n < 16; n++) v[n] = UPW[ln * 17 + n];
        fft_serial<16, false>(v, tw16);
#pragma unroll
        for (int n = 0; n < 16; n++) UPW[ln * 17 + brevn(n, 4)] = v[n];
    }
    __syncwarp();

    // Stage E: cols fwd -> natural-order packed spectrum
    if (h == 0) {
#pragma unroll
        for (int m = 0; m < 16; m++) v[m] = UPW[m * 17 + ln];
        fft_serial<16, false>(v, tw16);
#pragma unroll
        for (int m = 0; m < 16; m++) UPW[brevn(m, 4) * 17 + ln] = v[m];
    }
    __syncwarp();

    // Stage F: p8 = sub2(Zpacked * phi1), 2 outputs per lane
#pragma unroll
    for (int k = 0; k < 2; k++) {
        const int o = lane + 32 * k;
        const int u = o >> 3, vv = o & 7;
        float ar = 0.f, ai = 0.f;
#pragma unroll
        for (int i = 0; i < 2; i++)
#pragma unroll
            for (int j = 0; j < 2; j++) {
                const float p = PHI1[(8 * i + u) * 16 + 8 * j + vv];
                const float2 z = UPW[(8 * i + u) * 17 + 8 * j + vv];
                ar = fmaf(z.x, p, ar); ai = fmaf(z.y, p, ai);
            }
        P8W[w][o] = make_float2(0.25f * ar, 0.25f * ai);
    }
    __syncwarp();

    // Stage G1: separable ifft8 — row pass
#pragma unroll
    for (int k = 0; k < 2; k++) {
        const int o = lane + 32 * k;
        const int y = o >> 3, vv = o & 7;
        float ar = 0.f, ai = 0.f;
#pragma unroll
        for (int u = 0; u < 8; u++) {
            const float2 p = P8W[w][u * 8 + vv];
            const float2 w8 = tw8[(y * u) & 7];
            ar = fmaf(p.x, w8.x, fmaf(-p.y, w8.y, ar));
            ai = fmaf(p.y, w8.x, fmaf( p.x, w8.y, ai));
        }
        R8W[w][o] = make_float2(ar, ai);
    }
    __syncwarp();

    // Stage G2: col pass; Re -> channel chbase+2w, Im -> chbase+2w+1
    float* fb = g_feat + bc * 81 * 64;
#pragma unroll
    for (int k = 0; k < 2; k++) {
        const int o = lane + 32 * k;
        const int y = o >> 3, xx = o & 7;
        float ar = 0.f, ai = 0.f;
#pragma unroll
        for (int vv = 0; vv < 8; vv++) {
            const float2 p = R8W[w][y * 8 + vv];
            const float2 w8 = tw8[(xx * vv) & 7];
            ar = fmaf(p.x, w8.x, fmaf(-p.y, w8.y, ar));
            ai = fmaf(p.y, w8.x, fmaf( p.x, w8.y, ai));
        }
        fb[(chbase + 2 * w)     * 64 + o] = ar * (1.0f / 64.0f);
        fb[(chbase + 2 * w + 1) * 64 + o] = ai * (1.0f / 64.0f);
    }
}

// ---------------- K4: init + fused stats/GEMV with atomic finish ----------------
__global__ void __launch_bounds__(640)
k4_init(const float* __restrict__ bias, float* __restrict__ out) {
    const int t = threadIdx.x;
    if (t < 640) out[t] = bias[t % 10];
}

__global__ void __launch_bounds__(T256)
k4_gemv(const float* __restrict__ gamma, const float* __restrict__ beta,
        const float* __restrict__ W, float* __restrict__ out) {
    const int b = blockIdx.x / 9, c = blockIdx.x - (blockIdx.x / 9) * 9;
    const float* f = g_feat + b * 15552 + c * 1728;   // 3 complete groups of 576
    __shared__ float smu[3], srs[3];
    __shared__ float redA[3][2], redB[3][2];
    const int tid = threadIdx.x;

    if (tid < 192) {
        const int g = tid >> 6, l = tid & 63;
        float s = 0.f, s2 = 0.f;
#pragma unroll
        for (int i = l; i < 576; i += 64) {
            const float xv = f[g * 576 + i];
            s += xv; s2 = fmaf(xv, xv, s2);
        }
#pragma unroll
        for (int o = 16; o > 0; o >>= 1) {
            s  += __shfl_xor_sync(0xffffffffu, s,  o);
            s2 += __shfl_xor_sync(0xffffffffu, s2, o);
        }
        if ((l & 31) == 0) { redA[g][l >> 5] = s; redB[g][l >> 5] = s2; }
    }
    __syncthreads();
    if (tid < 3) {
        const float s = redA[tid][0] + redA[tid][1];
        const float s2 = redB[tid][0] + redB[tid][1];
        const float m = s * (1.0f / 576.0f);
        smu[tid] = m;
        srs[tid] = rsqrtf(s2 * (1.0f / 576.0f) - m * m + 1e-5f);
    }
    __syncthreads();

    float acc[10];
#pragma unroll
    for (int j = 0; j < 10; j++) acc[j] = 0.f;
    const float* Wc = W + c * 1728;
    for (int i = tid; i < 1728; i += T256) {
        const int l = i >> 6;
        const int gl = l / 9;
        const int ch = c * 27 + l;
        const float nv = (f[i] - smu[gl]) * srs[gl] * gamma[ch] + beta[ch];
#pragma unroll
        for (int j = 0; j < 10; j++)
            acc[j] = fmaf(nv, Wc[j * 15552 + i], acc[j]);
    }

    __shared__ float red[8][10];
    const int lane = tid & 31, wrp = tid >> 5;
#pragma unroll
    for (int j = 0; j < 10; j++) {
        float vv = acc[j];
#pragma unroll
        for (int o = 16; o > 0; o >>= 1) vv += __shfl_xor_sync(0xffffffffu, vv, o);
        if (lane == 0) red[wrp][j] = vv;
    }
    __syncthreads();
    if (tid < 10) {
        float vv = 0.f;
#pragma unroll
        for (int w = 0; w < 8; w++) vv += red[w][tid];
        atomicAdd(&out[b * 10 + tid], vv);
    }
}

// ---------------- launch ----------------
extern "C" void kernel_launch(void* const* d_in, const int* in_sizes, int n_in,
                              void* d_out, int out_size) {
    const float* x     = (const float*)d_in[0];
    const float* psi0  = (const float*)d_in[1];
    const float* psi1  = (const float*)d_in[2];
    const float* phi   = (const float*)d_in[3];
    const float* gamma = (const float*)d_in[4];
    const float* beta  = (const float*)d_in[5];
    const float* W     = (const float*)d_in[6];
    const float* bias  = (const float*)d_in[7];
    float* out = (float*)d_out;

    k4_init<<<1,        640 >>>(bias, out);
    k1_xf  <<<192,      T256>>>(x, phi);
    k2_u0f <<<384,      T128>>>(psi0, phi);
    k3_p16 <<<192 * 9,  T128>>>(psi1, phi);
    k4_gemv<<<64 * 9,   T256>>>(gamma, beta, W, out);
}